// round 5
// baseline (speedup 1.0000x reference)
#include <cuda_runtime.h>
#include <cuda_bf16.h>
#include <stdint.h>

#define B_DIM 64
#define S_DIM 512
#define H_DIM 1024
#define L_DIM 512
#define NEG_INF_F (-1e9f)

// ---------------------------------------------------------------------------
// Scratch (module-load allocations, allowed)
// ---------------------------------------------------------------------------
__device__ float         g_scores[(size_t)B_DIM * L_DIM * S_DIM];  // 67 MB
__device__ __nv_bfloat16 g_Xh[(size_t)B_DIM * S_DIM * H_DIM];
__device__ __nv_bfloat16 g_Xl[(size_t)B_DIM * S_DIM * H_DIM];
__device__ __nv_bfloat16 g_Wh[(size_t)L_DIM * H_DIM];
__device__ __nv_bfloat16 g_Wl[(size_t)L_DIM * H_DIM];
__device__ __nv_bfloat16 g_Ph[(size_t)B_DIM * L_DIM * S_DIM];
__device__ __nv_bfloat16 g_Pl[(size_t)B_DIM * L_DIM * S_DIM];

// ---------------------------------------------------------------------------
// Helpers
// ---------------------------------------------------------------------------
__device__ __forceinline__ uint32_t smem_u32(const void* p) {
    uint32_t a;
    asm("{ .reg .u64 t; cvta.to.shared.u64 t, %1; cvt.u32.u64 %0, t; }" : "=r"(a) : "l"(p));
    return a;
}

#define CP_ASYNC16(dst, src) \
    asm volatile("cp.async.cg.shared.global [%0], [%1], 16;" :: "r"(dst), "l"(src))
#define CP_COMMIT()  asm volatile("cp.async.commit_group;" ::: "memory")
#define CP_WAIT2()   asm volatile("cp.async.wait_group 2;" ::: "memory")

#define LDSM_X4(r0, r1, r2, r3, a) \
    asm volatile("ldmatrix.sync.aligned.m8n8.x4.shared.b16 {%0,%1,%2,%3}, [%4];" \
        : "=r"(r0), "=r"(r1), "=r"(r2), "=r"(r3) : "r"(a))
#define LDSM_X4T(r0, r1, r2, r3, a) \
    asm volatile("ldmatrix.sync.aligned.m8n8.x4.trans.shared.b16 {%0,%1,%2,%3}, [%4];" \
        : "=r"(r0), "=r"(r1), "=r"(r2), "=r"(r3) : "r"(a))

#define MMA_BF16(d, a0, a1, a2, a3, b0, b1) \
    asm volatile("mma.sync.aligned.m16n8k16.row.col.f32.bf16.bf16.f32 " \
        "{%0,%1,%2,%3},{%4,%5,%6,%7},{%8,%9},{%0,%1,%2,%3};" \
        : "+f"((d)[0]), "+f"((d)[1]), "+f"((d)[2]), "+f"((d)[3]) \
        : "r"(a0), "r"(a1), "r"(a2), "r"(a3), "r"(b0), "r"(b1))

// swizzles: 128B-row tiles (A, B K-major) and 256B-row tiles (B row-major)
#define SWZ128(o) ((o) ^ (((o) >> 3) & 0x70))
#define SWZ256(o) ((o) ^ (((o) >> 4) & 0x70))

__device__ __forceinline__ void split2(float v, __nv_bfloat16& h, __nv_bfloat16& l) {
    h = __float2bfloat16(v);
    l = __float2bfloat16(v - __bfloat162float(h));
}

// ---------------------------------------------------------------------------
// Converts: fp32 -> (hi, lo) bf16, flat, float4-vectorized
// ---------------------------------------------------------------------------
__global__ void convert_W(const float* __restrict__ W) {
    size_t i = ((size_t)blockIdx.x * 256 + threadIdx.x) * 4;
    float4 v = *reinterpret_cast<const float4*>(W + i);
    __nv_bfloat16 h0, l0, h1, l1, h2, l2, h3, l3;
    split2(v.x, h0, l0); split2(v.y, h1, l1); split2(v.z, h2, l2); split2(v.w, h3, l3);
    *reinterpret_cast<__nv_bfloat162*>(g_Wh + i)     = __nv_bfloat162{h0, h1};
    *reinterpret_cast<__nv_bfloat162*>(g_Wh + i + 2) = __nv_bfloat162{h2, h3};
    *reinterpret_cast<__nv_bfloat162*>(g_Wl + i)     = __nv_bfloat162{l0, l1};
    *reinterpret_cast<__nv_bfloat162*>(g_Wl + i + 2) = __nv_bfloat162{l2, l3};
}

__global__ void convert_X(const float* __restrict__ X) {
    size_t i = ((size_t)blockIdx.x * 256 + threadIdx.x) * 4;
    float4 v = *reinterpret_cast<const float4*>(X + i);
    __nv_bfloat16 h0, l0, h1, l1, h2, l2, h3, l3;
    split2(v.x, h0, l0); split2(v.y, h1, l1); split2(v.z, h2, l2); split2(v.w, h3, l3);
    *reinterpret_cast<__nv_bfloat162*>(g_Xh + i)     = __nv_bfloat162{h0, h1};
    *reinterpret_cast<__nv_bfloat162*>(g_Xh + i + 2) = __nv_bfloat162{h2, h3};
    *reinterpret_cast<__nv_bfloat162*>(g_Xl + i)     = __nv_bfloat162{l0, l1};
    *reinterpret_cast<__nv_bfloat162*>(g_Xl + i + 2) = __nv_bfloat162{l2, l3};
}

// ---------------------------------------------------------------------------
// bf16x3 split GEMM via mma.sync (HMMA), 128x128 tile, K-chunk 64, 8 warps.
// 3-stage cp.async pipeline (loads issued BEFORE the wait so wait_group 2
// provably completes the chunk being consumed), software-pipelined frags.
//   B_KMAJOR=true : B[n,k] row-major (NT GEMM)  -> ldmatrix non-trans
//   B_KMAJOR=false: B[k,n] row-major (NN GEMM)  -> ldmatrix trans
// smem: 3 stages x (Ah|Al|Bh|Bl) x 16KB = 192KB dynamic.
// ---------------------------------------------------------------------------
#define GEMM_SMEM (3 * 4 * 16384)

template <bool B_KMAJOR>
__global__ void __launch_bounds__(256, 1) gemm_hmma_x3(
    const __nv_bfloat16* __restrict__ Ah, const __nv_bfloat16* __restrict__ Al,
    const __nv_bfloat16* __restrict__ Bh, const __nv_bfloat16* __restrict__ Bl,
    float* __restrict__ D,
    int lda, int ldb, int ldd, int nk,
    size_t strideA, size_t strideB, size_t strideD)
{
    extern __shared__ char smem[];
    const uint32_t sb = smem_u32(smem);
    const int tid = threadIdx.x;
    const int wid = tid >> 5, lane = tid & 31;
    const int warp_m = wid & 3, warp_n = wid >> 2;
    const int b  = blockIdx.z;
    const int m0 = blockIdx.y * 128;
    const int n0 = blockIdx.x * 128;

    const __nv_bfloat16* tAh = Ah + (size_t)b * strideA + (size_t)m0 * lda;
    const __nv_bfloat16* tAl = Al + (size_t)b * strideA + (size_t)m0 * lda;
    const __nv_bfloat16* pBh = Bh + (size_t)b * strideB;
    const __nv_bfloat16* pBl = Bl + (size_t)b * strideB;

    float acc[2][8][4];
    #pragma unroll
    for (int i = 0; i < 2; ++i)
        #pragma unroll
        for (int j = 0; j < 8; ++j)
            #pragma unroll
            for (int q = 0; q < 4; ++q) acc[i][j][q] = 0.0f;

    // ---- stage loader (one commit_group per call) ----
    auto load_stage = [&](int c, int st) {
        const uint32_t base = sb + st * 65536;
        #pragma unroll
        for (int i = 0; i < 4; ++i) {
            int idx = i * 256 + tid;             // 0..1023
            int row = idx >> 3, sl = idx & 7;
            uint32_t doff = SWZ128(row * 128 + sl * 16);
            CP_ASYNC16(base + doff,         tAh + (size_t)row * lda + c * 64 + sl * 8);
            CP_ASYNC16(base + 16384 + doff, tAl + (size_t)row * lda + c * 64 + sl * 8);
        }
        if (B_KMAJOR) {
            const __nv_bfloat16* tBh = pBh + (size_t)n0 * ldb;
            const __nv_bfloat16* tBl = pBl + (size_t)n0 * ldb;
            #pragma unroll
            for (int i = 0; i < 4; ++i) {
                int idx = i * 256 + tid;
                int row = idx >> 3, sl = idx & 7;
                uint32_t doff = SWZ128(row * 128 + sl * 16);
                CP_ASYNC16(base + 32768 + doff, tBh + (size_t)row * ldb + c * 64 + sl * 8);
                CP_ASYNC16(base + 49152 + doff, tBl + (size_t)row * ldb + c * 64 + sl * 8);
            }
        } else {
            #pragma unroll
            for (int i = 0; i < 4; ++i) {
                int idx = i * 256 + tid;
                int row = idx >> 4, sl = idx & 15;
                uint32_t doff = SWZ256(row * 256 + sl * 16);
                CP_ASYNC16(base + 32768 + doff, pBh + (size_t)(c * 64 + row) * ldb + n0 + sl * 8);
                CP_ASYNC16(base + 49152 + doff, pBl + (size_t)(c * 64 + row) * ldb + n0 + sl * 8);
            }
        }
        CP_COMMIT();
    };

    // fragment double buffers
    uint32_t ah[2][2][4], al[2][2][4];   // [buf][mt][reg]
    uint32_t bh[2][8][2], bl[2][8][2];   // [buf][nt][reg]

    // frag fetch for one ks slice of the given stage into buffer fb
    auto load_frags = [&](int ks, uint32_t base, int fb) {
        const uint32_t sAh = base, sAl = base + 16384;
        const uint32_t sBh = base + 32768, sBl = base + 49152;
        #pragma unroll
        for (int mt = 0; mt < 2; ++mt) {
            int row = warp_m * 32 + mt * 16 + (lane & 15);
            uint32_t off = SWZ128(row * 128 + ks * 32 + ((lane >> 4) << 4));
            LDSM_X4(ah[fb][mt][0], ah[fb][mt][1], ah[fb][mt][2], ah[fb][mt][3], sAh + off);
            LDSM_X4(al[fb][mt][0], al[fb][mt][1], al[fb][mt][2], al[fb][mt][3], sAl + off);
        }
        #pragma unroll
        for (int nt2 = 0; nt2 < 4; ++nt2) {
            if (B_KMAJOR) {
                int row = warp_n * 64 + nt2 * 16 + ((lane >> 4) << 3) + (lane & 7);
                uint32_t off = SWZ128(row * 128 + ks * 32 + (((lane >> 3) & 1) << 4));
                LDSM_X4(bh[fb][2 * nt2][0], bh[fb][2 * nt2][1], bh[fb][2 * nt2 + 1][0], bh[fb][2 * nt2 + 1][1], sBh + off);
                LDSM_X4(bl[fb][2 * nt2][0], bl[fb][2 * nt2][1], bl[fb][2 * nt2 + 1][0], bl[fb][2 * nt2 + 1][1], sBl + off);
            } else {
                int krow = ks * 16 + (((lane >> 3) & 1) << 3) + (lane & 7);
                int col  = warp_n * 64 + nt2 * 16 + ((lane >> 4) << 3);
                uint32_t off = SWZ256(krow * 256 + col * 2);
                LDSM_X4T(bh[fb][2 * nt2][0], bh[fb][2 * nt2][1], bh[fb][2 * nt2 + 1][0], bh[fb][2 * nt2 + 1][1], sBh + off);
                LDSM_X4T(bl[fb][2 * nt2][0], bl[fb][2 * nt2][1], bl[fb][2 * nt2 + 1][0], bl[fb][2 * nt2 + 1][1], sBl + off);
            }
        }
    };

    auto do_mmas = [&](int fb) {
        #pragma unroll
        for (int mt = 0; mt < 2; ++mt)
            #pragma unroll
            for (int nt = 0; nt < 8; ++nt) {
                MMA_BF16(acc[mt][nt], ah[fb][mt][0], ah[fb][mt][1], ah[fb][mt][2], ah[fb][mt][3], bh[fb][nt][0], bh[fb][nt][1]);
                MMA_BF16(acc[mt][nt], ah[fb][mt][0], ah[fb][mt][1], ah[fb][mt][2], ah[fb][mt][3], bl[fb][nt][0], bl[fb][nt][1]);
                MMA_BF16(acc[mt][nt], al[fb][mt][0], al[fb][mt][1], al[fb][mt][2], al[fb][mt][3], bh[fb][nt][0], bh[fb][nt][1]);
            }
    };

    // prologue: stages 0, 1 in flight (2 commit groups)
    load_stage(0, 0);
    if (nk > 1) load_stage(1, 1); else CP_COMMIT();

    for (int c = 0; c < nk; ++c) {
        __syncthreads();     // WAR: all warps done computing chunk c-1, whose
                             // stage ((c+2)%3) is about to be refilled
        if (c + 2 < nk) load_stage(c + 2, (c + 2) % 3);
        else            CP_COMMIT();   // keep group count so WAIT2 drains chunk c
        CP_WAIT2();          // 3 groups in flight -> oldest (chunk c) complete
        __syncthreads();     // block-wide visibility of chunk c

        const uint32_t base = sb + (c % 3) * 65536;
        load_frags(0, base, 0);
        #pragma unroll
        for (int ks = 0; ks < 4; ++ks) {
            if (ks < 3) load_frags(ks + 1, base, (ks + 1) & 1);
            do_mmas(ks & 1);
        }
    }

    // epilogue
    float* Db = D + (size_t)b * strideD;
    #pragma unroll
    for (int mt = 0; mt < 2; ++mt) {
        int row = m0 + warp_m * 32 + mt * 16 + (lane >> 2);
        #pragma unroll
        for (int nt = 0; nt < 8; ++nt) {
            int col = n0 + warp_n * 64 + nt * 8 + (lane & 3) * 2;
            *reinterpret_cast<float2*>(Db + (size_t)row * ldd + col) =
                make_float2(acc[mt][nt][0], acc[mt][nt][1]);
            *reinterpret_cast<float2*>(Db + (size_t)(row + 8) * ldd + col) =
                make_float2(acc[mt][nt][2], acc[mt][nt][3]);
        }
    }
}

// ---------------------------------------------------------------------------
// Masked softmax over S; reads g_scores (f32), writes split probs (Ph, Pl).
// One warp per (b,l) row.
// ---------------------------------------------------------------------------
__global__ void __launch_bounds__(256) softmax_split(const int* __restrict__ mask)
{
    const int row  = blockIdx.x * 8 + (threadIdx.x >> 5);
    const int lane = threadIdx.x & 31;
    const int b    = row >> 9;

    const float* p  = g_scores + (size_t)row * S_DIM;
    const int* mrow = mask + (size_t)b * S_DIM;

    float4 fv[4];
    float mx = -3e38f;
    #pragma unroll
    for (int c = 0; c < 4; ++c) {
        const int s = c * 128 + lane * 4;
        float4 x = *reinterpret_cast<const float4*>(p + s);
        int4 mm = *reinterpret_cast<const int4*>(mrow + s);
        x.x = (mm.x == 0) ? NEG_INF_F : x.x;
        x.y = (mm.y == 0) ? NEG_INF_F : x.y;
        x.z = (mm.z == 0) ? NEG_INF_F : x.z;
        x.w = (mm.w == 0) ? NEG_INF_F : x.w;
        fv[c] = x;
        mx = fmaxf(mx, fmaxf(fmaxf(x.x, x.y), fmaxf(x.z, x.w)));
    }
    #pragma unroll
    for (int o = 16; o > 0; o >>= 1) mx = fmaxf(mx, __shfl_xor_sync(0xffffffffu, mx, o));

    float sum = 0.0f;
    #pragma unroll
    for (int c = 0; c < 4; ++c) {
        fv[c].x = expf(fv[c].x - mx); fv[c].y = expf(fv[c].y - mx);
        fv[c].z = expf(fv[c].z - mx); fv[c].w = expf(fv[c].w - mx);
        sum += fv[c].x + fv[c].y + fv[c].z + fv[c].w;
    }
    #pragma unroll
    for (int o = 16; o > 0; o >>= 1) sum += __shfl_xor_sync(0xffffffffu, sum, o);

    const float inv = 1.0f / sum;
    #pragma unroll
    for (int c = 0; c < 4; ++c) {
        const int s = c * 128 + lane * 4;
        float v0 = fv[c].x * inv, v1 = fv[c].y * inv, v2 = fv[c].z * inv, v3 = fv[c].w * inv;
        __nv_bfloat16 h0, l0, h1, l1, h2, l2, h3, l3;
        split2(v0, h0, l0); split2(v1, h1, l1); split2(v2, h2, l2); split2(v3, h3, l3);
        __nv_bfloat162* ph = reinterpret_cast<__nv_bfloat162*>(g_Ph + (size_t)row * S_DIM + s);
        __nv_bfloat162* pl = reinterpret_cast<__nv_bfloat162*>(g_Pl + (size_t)row * S_DIM + s);
        ph[0] = __nv_bfloat162{h0, h1}; ph[1] = __nv_bfloat162{h2, h3};
        pl[0] = __nv_bfloat162{l0, l1}; pl[1] = __nv_bfloat162{l2, l3};
    }
}

// ---------------------------------------------------------------------------
// Launch
// ---------------------------------------------------------------------------
extern "C" void kernel_launch(void* const* d_in, const int* in_sizes, int n_in,
                              void* d_out, int out_size)
{
    const float* X    = (const float*)d_in[0];   // [B, S, H]
    const int*   mask = (const int*)  d_in[1];   // [B, S]
    const float* W    = (const float*)d_in[2];   // [L, H]
    float* out = (float*)d_out;                  // [B, L, H]

    cudaFuncSetAttribute(gemm_hmma_x3<true>,  cudaFuncAttributeMaxDynamicSharedMemorySize, GEMM_SMEM);
    cudaFuncSetAttribute(gemm_hmma_x3<false>, cudaFuncAttributeMaxDynamicSharedMemorySize, GEMM_SMEM);

    void *pXh, *pXl, *pWh, *pWl, *pPh, *pPl, *pSc;
    cudaGetSymbolAddress(&pXh, g_Xh); cudaGetSymbolAddress(&pXl, g_Xl);
    cudaGetSymbolAddress(&pWh, g_Wh); cudaGetSymbolAddress(&pWl, g_Wl);
    cudaGetSymbolAddress(&pPh, g_Ph); cudaGetSymbolAddress(&pPl, g_Pl);
    cudaGetSymbolAddress(&pSc, g_scores);

    convert_W<<<(L_DIM * H_DIM) / 1024, 256>>>(W);
    convert_X<<<((size_t)B_DIM * S_DIM * H_DIM) / 1024, 256>>>(X);

    // GEMM1 (NT): scores[b,l,s] = W[l,:] . X[b,s,:]   M=L, N=S, K=H
    gemm_hmma_x3<true><<<dim3(S_DIM / 128, L_DIM / 128, B_DIM), 256, GEMM_SMEM>>>(
        (const __nv_bfloat16*)pWh, (const __nv_bfloat16*)pWl,
        (const __nv_bfloat16*)pXh, (const __nv_bfloat16*)pXl,
        (float*)pSc,
        H_DIM, H_DIM, S_DIM, H_DIM / 64,
        0, (size_t)S_DIM * H_DIM, (size_t)L_DIM * S_DIM);

    softmax_split<<<(B_DIM * L_DIM) / 8, 256>>>(mask);

    // GEMM2 (NN): out[b,l,h] = P[b,l,:] . X[b,:,h]    M=L, N=H, K=S
    gemm_hmma_x3<false><<<dim3(H_DIM / 128, L_DIM / 128, B_DIM), 256, GEMM_SMEM>>>(
        (const __nv_bfloat16*)pPh, (const __nv_bfloat16*)pPl,
        (const __nv_bfloat16*)pXh, (const __nv_bfloat16*)pXl,
        out,
        S_DIM, H_DIM, H_DIM, S_DIM / 64,
        (size_t)L_DIM * S_DIM, (size_t)S_DIM * H_DIM, (size_t)L_DIM * H_DIM);
}

// round 6
// speedup vs baseline: 1.0223x; 1.0223x over previous
#include <cuda_runtime.h>
#include <cuda_bf16.h>
#include <stdint.h>

#define B_DIM 64
#define S_DIM 512
#define H_DIM 1024
#define L_DIM 512
#define NEG_INF_F (-1e9f)

// ---------------------------------------------------------------------------
// Scratch (module-load allocations, allowed)
// ---------------------------------------------------------------------------
__device__ float         g_scores[(size_t)B_DIM * L_DIM * S_DIM];  // 67 MB
__device__ __nv_bfloat16 g_Xh[(size_t)B_DIM * S_DIM * H_DIM];
__device__ __nv_bfloat16 g_Xl[(size_t)B_DIM * S_DIM * H_DIM];
__device__ __nv_bfloat16 g_Wh[(size_t)L_DIM * H_DIM];
__device__ __nv_bfloat16 g_Wl[(size_t)L_DIM * H_DIM];
__device__ __nv_bfloat16 g_Ph[(size_t)B_DIM * L_DIM * S_DIM];
__device__ __nv_bfloat16 g_Pl[(size_t)B_DIM * L_DIM * S_DIM];

// ---------------------------------------------------------------------------
// Helpers
// ---------------------------------------------------------------------------
__device__ __forceinline__ uint32_t smem_u32(const void* p) {
    uint32_t a;
    asm("{ .reg .u64 t; cvta.to.shared.u64 t, %1; cvt.u32.u64 %0, t; }" : "=r"(a) : "l"(p));
    return a;
}

#define CP_ASYNC16(dst, src) \
    asm volatile("cp.async.cg.shared.global [%0], [%1], 16;" :: "r"(dst), "l"(src))
#define CP_COMMIT()  asm volatile("cp.async.commit_group;" ::: "memory")
#define CP_WAIT1()   asm volatile("cp.async.wait_group 1;" ::: "memory")

#define LDSM_X4(r0, r1, r2, r3, a) \
    asm volatile("ldmatrix.sync.aligned.m8n8.x4.shared.b16 {%0,%1,%2,%3}, [%4];" \
        : "=r"(r0), "=r"(r1), "=r"(r2), "=r"(r3) : "r"(a))
#define LDSM_X4T(r0, r1, r2, r3, a) \
    asm volatile("ldmatrix.sync.aligned.m8n8.x4.trans.shared.b16 {%0,%1,%2,%3}, [%4];" \
        : "=r"(r0), "=r"(r1), "=r"(r2), "=r"(r3) : "r"(a))

#define MMA_BF16(d, a0, a1, a2, a3, b0, b1) \
    asm volatile("mma.sync.aligned.m16n8k16.row.col.f32.bf16.bf16.f32 " \
        "{%0,%1,%2,%3},{%4,%5,%6,%7},{%8,%9},{%0,%1,%2,%3};" \
        : "+f"((d)[0]), "+f"((d)[1]), "+f"((d)[2]), "+f"((d)[3]) \
        : "r"(a0), "r"(a1), "r"(a2), "r"(a3), "r"(b0), "r"(b1))

// swizzles: 128B-row tiles (A, B K-major) and 256B-row tiles (B row-major)
#define SWZ128(o) ((o) ^ (((o) >> 3) & 0x70))
#define SWZ256(o) ((o) ^ (((o) >> 4) & 0x70))

__device__ __forceinline__ void split2(float v, __nv_bfloat16& h, __nv_bfloat16& l) {
    h = __float2bfloat16(v);
    l = __float2bfloat16(v - __bfloat162float(h));
}

// ---------------------------------------------------------------------------
// Converts: fp32 -> (hi, lo) bf16, flat, float4-vectorized
// ---------------------------------------------------------------------------
__global__ void convert_W(const float* __restrict__ W) {
    size_t i = ((size_t)blockIdx.x * 256 + threadIdx.x) * 4;
    float4 v = *reinterpret_cast<const float4*>(W + i);
    __nv_bfloat16 h0, l0, h1, l1, h2, l2, h3, l3;
    split2(v.x, h0, l0); split2(v.y, h1, l1); split2(v.z, h2, l2); split2(v.w, h3, l3);
    *reinterpret_cast<__nv_bfloat162*>(g_Wh + i)     = __nv_bfloat162{h0, h1};
    *reinterpret_cast<__nv_bfloat162*>(g_Wh + i + 2) = __nv_bfloat162{h2, h3};
    *reinterpret_cast<__nv_bfloat162*>(g_Wl + i)     = __nv_bfloat162{l0, l1};
    *reinterpret_cast<__nv_bfloat162*>(g_Wl + i + 2) = __nv_bfloat162{l2, l3};
}

__global__ void convert_X(const float* __restrict__ X) {
    size_t i = ((size_t)blockIdx.x * 256 + threadIdx.x) * 4;
    float4 v = *reinterpret_cast<const float4*>(X + i);
    __nv_bfloat16 h0, l0, h1, l1, h2, l2, h3, l3;
    split2(v.x, h0, l0); split2(v.y, h1, l1); split2(v.z, h2, l2); split2(v.w, h3, l3);
    *reinterpret_cast<__nv_bfloat162*>(g_Xh + i)     = __nv_bfloat162{h0, h1};
    *reinterpret_cast<__nv_bfloat162*>(g_Xh + i + 2) = __nv_bfloat162{h2, h3};
    *reinterpret_cast<__nv_bfloat162*>(g_Xl + i)     = __nv_bfloat162{l0, l1};
    *reinterpret_cast<__nv_bfloat162*>(g_Xl + i + 2) = __nv_bfloat162{l2, l3};
}

// ---------------------------------------------------------------------------
// bf16x3 split GEMM via mma.sync (HMMA).
// CTA tile 256(M) x 128(N), K-chunk 64, 8 warps (4M x 2N), warp tile 64x64.
// 2-stage cp.async pipeline (R3-proven ordering).
//   B_KMAJOR=true : B[n,k] row-major (NT GEMM)  -> ldmatrix non-trans
//   B_KMAJOR=false: B[k,n] row-major (NN GEMM)  -> ldmatrix trans
// smem/stage: Ah 32K | Al 32K | Bh 16K | Bl 16K = 96KB; 2 stages = 192KB.
// ---------------------------------------------------------------------------
#define STAGE_BYTES 98304
#define GEMM_SMEM   (2 * STAGE_BYTES)

template <bool B_KMAJOR>
__global__ void __launch_bounds__(256, 1) gemm_hmma_x3(
    const __nv_bfloat16* __restrict__ Ah, const __nv_bfloat16* __restrict__ Al,
    const __nv_bfloat16* __restrict__ Bh, const __nv_bfloat16* __restrict__ Bl,
    float* __restrict__ D,
    int lda, int ldb, int ldd, int nk,
    size_t strideA, size_t strideB, size_t strideD)
{
    extern __shared__ char smem[];
    const uint32_t sb = smem_u32(smem);
    const int tid = threadIdx.x;
    const int wid = tid >> 5, lane = tid & 31;
    const int warp_m = wid & 3, warp_n = wid >> 2;   // 4M x 2N warps
    const int b  = blockIdx.z;
    const int m0 = blockIdx.y * 256;
    const int n0 = blockIdx.x * 128;

    const __nv_bfloat16* tAh = Ah + (size_t)b * strideA + (size_t)m0 * lda;
    const __nv_bfloat16* tAl = Al + (size_t)b * strideA + (size_t)m0 * lda;
    const __nv_bfloat16* pBh = Bh + (size_t)b * strideB;
    const __nv_bfloat16* pBl = Bl + (size_t)b * strideB;

    float acc[4][8][4];
    #pragma unroll
    for (int i = 0; i < 4; ++i)
        #pragma unroll
        for (int j = 0; j < 8; ++j)
            #pragma unroll
            for (int q = 0; q < 4; ++q) acc[i][j][q] = 0.0f;

    // ---- stage loader (one commit_group per call) ----
    auto load_stage = [&](int c, int st) {
        const uint32_t base = sb + st * STAGE_BYTES;
        // A halves: 256 rows x 64 k, 128B rows -> 2048 slices each
        #pragma unroll
        for (int i = 0; i < 8; ++i) {
            int idx = i * 256 + tid;
            int row = idx >> 3, sl = idx & 7;
            uint32_t doff = SWZ128(row * 128 + sl * 16);
            CP_ASYNC16(base + doff,         tAh + (size_t)row * lda + c * 64 + sl * 8);
            CP_ASYNC16(base + 32768 + doff, tAl + (size_t)row * lda + c * 64 + sl * 8);
        }
        if (B_KMAJOR) {
            const __nv_bfloat16* tBh = pBh + (size_t)n0 * ldb;
            const __nv_bfloat16* tBl = pBl + (size_t)n0 * ldb;
            #pragma unroll
            for (int i = 0; i < 4; ++i) {
                int idx = i * 256 + tid;
                int row = idx >> 3, sl = idx & 7;
                uint32_t doff = SWZ128(row * 128 + sl * 16);
                CP_ASYNC16(base + 65536 + doff, tBh + (size_t)row * ldb + c * 64 + sl * 8);
                CP_ASYNC16(base + 81920 + doff, tBl + (size_t)row * ldb + c * 64 + sl * 8);
            }
        } else {
            // B halves: 64 k-rows x 128 n, 256B rows -> 1024 slices each
            #pragma unroll
            for (int i = 0; i < 4; ++i) {
                int idx = i * 256 + tid;
                int row = idx >> 4, sl = idx & 15;
                uint32_t doff = SWZ256(row * 256 + sl * 16);
                CP_ASYNC16(base + 65536 + doff, pBh + (size_t)(c * 64 + row) * ldb + n0 + sl * 8);
                CP_ASYNC16(base + 81920 + doff, pBl + (size_t)(c * 64 + row) * ldb + n0 + sl * 8);
            }
        }
        CP_COMMIT();
    };

    // prologue
    load_stage(0, 0);

    for (int c = 0; c < nk; ++c) {
        if (c + 1 < nk) load_stage(c + 1, (c + 1) & 1);
        else            CP_COMMIT();     // empty group so WAIT1 drains chunk c
        CP_WAIT1();
        __syncthreads();

        const uint32_t base = sb + (c & 1) * STAGE_BYTES;
        const uint32_t sAh = base, sAl = base + 32768;
        const uint32_t sBh = base + 65536, sBl = base + 81920;

        #pragma unroll
        for (int ks = 0; ks < 4; ++ks) {
            // A fragments: 4 m-tiles x {h,l}
            uint32_t ah[4][4], al[4][4];
            #pragma unroll
            for (int mt = 0; mt < 4; ++mt) {
                int row = warp_m * 64 + mt * 16 + (lane & 15);
                uint32_t off = SWZ128(row * 128 + ks * 32 + ((lane >> 4) << 4));
                LDSM_X4(ah[mt][0], ah[mt][1], ah[mt][2], ah[mt][3], sAh + off);
                LDSM_X4(al[mt][0], al[mt][1], al[mt][2], al[mt][3], sAl + off);
            }
            // B fragments: 8 n8-tiles x {h,l}
            uint32_t bh[8][2], bl[8][2];
            #pragma unroll
            for (int nt2 = 0; nt2 < 4; ++nt2) {
                if (B_KMAJOR) {
                    int row = warp_n * 64 + nt2 * 16 + ((lane >> 4) << 3) + (lane & 7);
                    uint32_t off = SWZ128(row * 128 + ks * 32 + (((lane >> 3) & 1) << 4));
                    LDSM_X4(bh[2 * nt2][0], bh[2 * nt2][1], bh[2 * nt2 + 1][0], bh[2 * nt2 + 1][1], sBh + off);
                    LDSM_X4(bl[2 * nt2][0], bl[2 * nt2][1], bl[2 * nt2 + 1][0], bl[2 * nt2 + 1][1], sBl + off);
                } else {
                    int krow = ks * 16 + (((lane >> 3) & 1) << 3) + (lane & 7);
                    int col  = warp_n * 64 + nt2 * 16 + ((lane >> 4) << 3);
                    uint32_t off = SWZ256(krow * 256 + col * 2);
                    LDSM_X4T(bh[2 * nt2][0], bh[2 * nt2][1], bh[2 * nt2 + 1][0], bh[2 * nt2 + 1][1], sBh + off);
                    LDSM_X4T(bl[2 * nt2][0], bl[2 * nt2][1], bl[2 * nt2 + 1][0], bl[2 * nt2 + 1][1], sBl + off);
                }
            }
            // 3 products: 96 MMAs
            #pragma unroll
            for (int mt = 0; mt < 4; ++mt)
                #pragma unroll
                for (int nt = 0; nt < 8; ++nt) {
                    MMA_BF16(acc[mt][nt], ah[mt][0], ah[mt][1], ah[mt][2], ah[mt][3], bh[nt][0], bh[nt][1]);
                    MMA_BF16(acc[mt][nt], ah[mt][0], ah[mt][1], ah[mt][2], ah[mt][3], bl[nt][0], bl[nt][1]);
                    MMA_BF16(acc[mt][nt], al[mt][0], al[mt][1], al[mt][2], al[mt][3], bh[nt][0], bh[nt][1]);
                }
        }
        __syncthreads();
    }

    // epilogue
    float* Db = D + (size_t)b * strideD;
    #pragma unroll
    for (int mt = 0; mt < 4; ++mt) {
        int row = m0 + warp_m * 64 + mt * 16 + (lane >> 2);
        #pragma unroll
        for (int nt = 0; nt < 8; ++nt) {
            int col = n0 + warp_n * 64 + nt * 8 + (lane & 3) * 2;
            *reinterpret_cast<float2*>(Db + (size_t)row * ldd + col) =
                make_float2(acc[mt][nt][0], acc[mt][nt][1]);
            *reinterpret_cast<float2*>(Db + (size_t)(row + 8) * ldd + col) =
                make_float2(acc[mt][nt][2], acc[mt][nt][3]);
        }
    }
}

// ---------------------------------------------------------------------------
// Masked softmax over S; reads g_scores (f32), writes split probs (Ph, Pl).
// One warp per (b,l) row.
// ---------------------------------------------------------------------------
__global__ void __launch_bounds__(256) softmax_split(const int* __restrict__ mask)
{
    const int row  = blockIdx.x * 8 + (threadIdx.x >> 5);
    const int lane = threadIdx.x & 31;
    const int b    = row >> 9;

    const float* p  = g_scores + (size_t)row * S_DIM;
    const int* mrow = mask + (size_t)b * S_DIM;

    float4 fv[4];
    float mx = -3e38f;
    #pragma unroll
    for (int c = 0; c < 4; ++c) {
        const int s = c * 128 + lane * 4;
        float4 x = *reinterpret_cast<const float4*>(p + s);
        int4 mm = *reinterpret_cast<const int4*>(mrow + s);
        x.x = (mm.x == 0) ? NEG_INF_F : x.x;
        x.y = (mm.y == 0) ? NEG_INF_F : x.y;
        x.z = (mm.z == 0) ? NEG_INF_F : x.z;
        x.w = (mm.w == 0) ? NEG_INF_F : x.w;
        fv[c] = x;
        mx = fmaxf(mx, fmaxf(fmaxf(x.x, x.y), fmaxf(x.z, x.w)));
    }
    #pragma unroll
    for (int o = 16; o > 0; o >>= 1) mx = fmaxf(mx, __shfl_xor_sync(0xffffffffu, mx, o));

    float sum = 0.0f;
    #pragma unroll
    for (int c = 0; c < 4; ++c) {
        fv[c].x = expf(fv[c].x - mx); fv[c].y = expf(fv[c].y - mx);
        fv[c].z = expf(fv[c].z - mx); fv[c].w = expf(fv[c].w - mx);
        sum += fv[c].x + fv[c].y + fv[c].z + fv[c].w;
    }
    #pragma unroll
    for (int o = 16; o > 0; o >>= 1) sum += __shfl_xor_sync(0xffffffffu, sum, o);

    const float inv = 1.0f / sum;
    #pragma unroll
    for (int c = 0; c < 4; ++c) {
        const int s = c * 128 + lane * 4;
        float v0 = fv[c].x * inv, v1 = fv[c].y * inv, v2 = fv[c].z * inv, v3 = fv[c].w * inv;
        __nv_bfloat16 h0, l0, h1, l1, h2, l2, h3, l3;
        split2(v0, h0, l0); split2(v1, h1, l1); split2(v2, h2, l2); split2(v3, h3, l3);
        __nv_bfloat162* ph = reinterpret_cast<__nv_bfloat162*>(g_Ph + (size_t)row * S_DIM + s);
        __nv_bfloat162* pl = reinterpret_cast<__nv_bfloat162*>(g_Pl + (size_t)row * S_DIM + s);
        ph[0] = __nv_bfloat162{h0, h1}; ph[1] = __nv_bfloat162{h2, h3};
        pl[0] = __nv_bfloat162{l0, l1}; pl[1] = __nv_bfloat162{l2, l3};
    }
}

// ---------------------------------------------------------------------------
// Launch
// ---------------------------------------------------------------------------
extern "C" void kernel_launch(void* const* d_in, const int* in_sizes, int n_in,
                              void* d_out, int out_size)
{
    const float* X    = (const float*)d_in[0];   // [B, S, H]
    const int*   mask = (const int*)  d_in[1];   // [B, S]
    const float* W    = (const float*)d_in[2];   // [L, H]
    float* out = (float*)d_out;                  // [B, L, H]

    cudaFuncSetAttribute(gemm_hmma_x3<true>,  cudaFuncAttributeMaxDynamicSharedMemorySize, GEMM_SMEM);
    cudaFuncSetAttribute(gemm_hmma_x3<false>, cudaFuncAttributeMaxDynamicSharedMemorySize, GEMM_SMEM);

    void *pXh, *pXl, *pWh, *pWl, *pPh, *pPl, *pSc;
    cudaGetSymbolAddress(&pXh, g_Xh); cudaGetSymbolAddress(&pXl, g_Xl);
    cudaGetSymbolAddress(&pWh, g_Wh); cudaGetSymbolAddress(&pWl, g_Wl);
    cudaGetSymbolAddress(&pPh, g_Ph); cudaGetSymbolAddress(&pPl, g_Pl);
    cudaGetSymbolAddress(&pSc, g_scores);

    convert_W<<<(L_DIM * H_DIM) / 1024, 256>>>(W);
    convert_X<<<((size_t)B_DIM * S_DIM * H_DIM) / 1024, 256>>>(X);

    // GEMM1 (NT): scores[b,l,s] = W[l,:] . X[b,s,:]   M=L, N=S, K=H
    gemm_hmma_x3<true><<<dim3(S_DIM / 128, L_DIM / 256, B_DIM), 256, GEMM_SMEM>>>(
        (const __nv_bfloat16*)pWh, (const __nv_bfloat16*)pWl,
        (const __nv_bfloat16*)pXh, (const __nv_bfloat16*)pXl,
        (float*)pSc,
        H_DIM, H_DIM, S_DIM, H_DIM / 64,
        0, (size_t)S_DIM * H_DIM, (size_t)L_DIM * S_DIM);

    softmax_split<<<(B_DIM * L_DIM) / 8, 256>>>(mask);

    // GEMM2 (NN): out[b,l,h] = P[b,l,:] . X[b,:,h]    M=L, N=H, K=S
    gemm_hmma_x3<false><<<dim3(H_DIM / 128, L_DIM / 256, B_DIM), 256, GEMM_SMEM>>>(
        (const __nv_bfloat16*)pPh, (const __nv_bfloat16*)pPl,
        (const __nv_bfloat16*)pXh, (const __nv_bfloat16*)pXl,
        out,
        S_DIM, H_DIM, H_DIM, S_DIM / 64,
        (size_t)L_DIM * S_DIM, (size_t)S_DIM * H_DIM, (size_t)L_DIM * H_DIM);
}

// round 7
// speedup vs baseline: 1.4281x; 1.3969x over previous
#include <cuda_runtime.h>
#include <cuda_bf16.h>
#include <stdint.h>

#define B_DIM 64
#define S_DIM 512
#define H_DIM 1024
#define L_DIM 512
#define NEG_INF_F (-1e9f)

// ---------------------------------------------------------------------------
// Scratch (module-load allocations, allowed)
// ---------------------------------------------------------------------------
__device__ float         g_scores[(size_t)B_DIM * L_DIM * S_DIM];  // 67 MB
__device__ __nv_bfloat16 g_Xh[(size_t)B_DIM * S_DIM * H_DIM];      // compacted
__device__ __nv_bfloat16 g_Xl[(size_t)B_DIM * S_DIM * H_DIM];      // compacted
__device__ __nv_bfloat16 g_Wh[(size_t)L_DIM * H_DIM];
__device__ __nv_bfloat16 g_Wl[(size_t)L_DIM * H_DIM];
__device__ __nv_bfloat16 g_Ph[(size_t)B_DIM * L_DIM * S_DIM];      // compacted K
__device__ __nv_bfloat16 g_Pl[(size_t)B_DIM * L_DIM * S_DIM];
__device__ int g_idx[B_DIM * S_DIM];   // compacted s-index per batch
__device__ int g_cnt[B_DIM];           // # unmasked per batch
__device__ int g_npad[B_DIM];          // cnt rounded up to 64

// ---------------------------------------------------------------------------
// Helpers
// ---------------------------------------------------------------------------
__device__ __forceinline__ uint32_t smem_u32(const void* p) {
    uint32_t a;
    asm("{ .reg .u64 t; cvta.to.shared.u64 t, %1; cvt.u32.u64 %0, t; }" : "=r"(a) : "l"(p));
    return a;
}

#define CP_ASYNC16(dst, src) \
    asm volatile("cp.async.cg.shared.global [%0], [%1], 16;" :: "r"(dst), "l"(src))
#define CP_COMMIT()  asm volatile("cp.async.commit_group;" ::: "memory")
#define CP_WAIT1()   asm volatile("cp.async.wait_group 1;" ::: "memory")

#define LDSM_X4(r0, r1, r2, r3, a) \
    asm volatile("ldmatrix.sync.aligned.m8n8.x4.shared.b16 {%0,%1,%2,%3}, [%4];" \
        : "=r"(r0), "=r"(r1), "=r"(r2), "=r"(r3) : "r"(a))
#define LDSM_X4T(r0, r1, r2, r3, a) \
    asm volatile("ldmatrix.sync.aligned.m8n8.x4.trans.shared.b16 {%0,%1,%2,%3}, [%4];" \
        : "=r"(r0), "=r"(r1), "=r"(r2), "=r"(r3) : "r"(a))

#define MMA_BF16(d, a0, a1, a2, a3, b0, b1) \
    asm volatile("mma.sync.aligned.m16n8k16.row.col.f32.bf16.bf16.f32 " \
        "{%0,%1,%2,%3},{%4,%5,%6,%7},{%8,%9},{%0,%1,%2,%3};" \
        : "+f"((d)[0]), "+f"((d)[1]), "+f"((d)[2]), "+f"((d)[3]) \
        : "r"(a0), "r"(a1), "r"(a2), "r"(a3), "r"(b0), "r"(b1))

#define SWZ128(o) ((o) ^ (((o) >> 3) & 0x70))
#define SWZ256(o) ((o) ^ (((o) >> 4) & 0x70))

__device__ __forceinline__ void split2(float v, __nv_bfloat16& h, __nv_bfloat16& l) {
    h = __float2bfloat16(v);
    l = __float2bfloat16(v - __bfloat162float(h));
}

// ---------------------------------------------------------------------------
// Mask compaction: one block of 512 threads per batch.
// ---------------------------------------------------------------------------
__global__ void __launch_bounds__(512) compact_mask(const int* __restrict__ mask) {
    const int b = blockIdx.x, tid = threadIdx.x;
    const int lane = tid & 31, w = tid >> 5;
    const int m = (mask[(size_t)b * S_DIM + tid] != 0);
    const unsigned bal = __ballot_sync(0xffffffffu, m);

    __shared__ int ws[16], woff[16];
    if (lane == 0) ws[w] = __popc(bal);
    __syncthreads();
    if (tid == 0) {
        int s = 0;
        #pragma unroll
        for (int i = 0; i < 16; ++i) { woff[i] = s; s += ws[i]; }
        g_cnt[b]  = s;
        int np = ((s + 63) >> 6) << 6;
        g_npad[b] = (np < 64) ? 64 : np;
    }
    __syncthreads();
    if (m) {
        int pos = woff[w] + __popc(bal & ((1u << lane) - 1u));
        g_idx[b * S_DIM + pos] = tid;
    }
}

// ---------------------------------------------------------------------------
// Gather + split-convert X: Xc[b, j, :] = split(X[b, idx[b][j], :]); zeros for
// j >= cnt. One block per (j, b) row.
// ---------------------------------------------------------------------------
__global__ void __launch_bounds__(256) gather_convert_X(const float* __restrict__ X) {
    const int j = blockIdx.x, b = blockIdx.y;
    const int cnt = g_cnt[b];
    const size_t o = ((size_t)b * S_DIM + j) * H_DIM + threadIdx.x * 4;
    if (j < cnt) {
        const int s = g_idx[b * S_DIM + j];
        float4 v = *reinterpret_cast<const float4*>(X + ((size_t)b * S_DIM + s) * H_DIM + threadIdx.x * 4);
        __nv_bfloat16 h0, l0, h1, l1, h2, l2, h3, l3;
        split2(v.x, h0, l0); split2(v.y, h1, l1); split2(v.z, h2, l2); split2(v.w, h3, l3);
        *reinterpret_cast<__nv_bfloat162*>(g_Xh + o)     = __nv_bfloat162{h0, h1};
        *reinterpret_cast<__nv_bfloat162*>(g_Xh + o + 2) = __nv_bfloat162{h2, h3};
        *reinterpret_cast<__nv_bfloat162*>(g_Xl + o)     = __nv_bfloat162{l0, l1};
        *reinterpret_cast<__nv_bfloat162*>(g_Xl + o + 2) = __nv_bfloat162{l2, l3};
    } else {
        *reinterpret_cast<uint2*>(g_Xh + o) = make_uint2(0, 0);
        *reinterpret_cast<uint2*>(g_Xl + o) = make_uint2(0, 0);
    }
}

__global__ void convert_W(const float* __restrict__ W) {
    size_t i = ((size_t)blockIdx.x * 256 + threadIdx.x) * 4;
    float4 v = *reinterpret_cast<const float4*>(W + i);
    __nv_bfloat16 h0, l0, h1, l1, h2, l2, h3, l3;
    split2(v.x, h0, l0); split2(v.y, h1, l1); split2(v.z, h2, l2); split2(v.w, h3, l3);
    *reinterpret_cast<__nv_bfloat162*>(g_Wh + i)     = __nv_bfloat162{h0, h1};
    *reinterpret_cast<__nv_bfloat162*>(g_Wh + i + 2) = __nv_bfloat162{h2, h3};
    *reinterpret_cast<__nv_bfloat162*>(g_Wl + i)     = __nv_bfloat162{l0, l1};
    *reinterpret_cast<__nv_bfloat162*>(g_Wl + i + 2) = __nv_bfloat162{l2, l3};
}

// ---------------------------------------------------------------------------
// bf16x3 split GEMM via mma.sync. CTA 256(M) x 128(N), K-chunk 64, 8 warps,
// warp tile 64x64. 2-stage cp.async pipeline.
//   N_LIM: skip CTA if n0 >= g_npad[b]  (GEMM1, compacted N)
//   K_DYN: nk = g_npad[b] / 64          (GEMM2, compacted K)
// ---------------------------------------------------------------------------
#define STAGE_BYTES 98304
#define GEMM_SMEM   (2 * STAGE_BYTES)

template <bool B_KMAJOR, bool N_LIM, bool K_DYN>
__global__ void __launch_bounds__(256, 1) gemm_hmma_x3(
    const __nv_bfloat16* __restrict__ Ah, const __nv_bfloat16* __restrict__ Al,
    const __nv_bfloat16* __restrict__ Bh, const __nv_bfloat16* __restrict__ Bl,
    float* __restrict__ D,
    int lda, int ldb, int ldd, int nk,
    size_t strideA, size_t strideB, size_t strideD)
{
    extern __shared__ char smem[];
    const uint32_t sb = smem_u32(smem);
    const int tid = threadIdx.x;
    const int wid = tid >> 5, lane = tid & 31;
    const int warp_m = wid & 3, warp_n = wid >> 2;
    const int b  = blockIdx.z;
    const int m0 = blockIdx.y * 256;
    const int n0 = blockIdx.x * 128;

    if (N_LIM && n0 >= g_npad[b]) return;
    if (K_DYN) nk = g_npad[b] >> 6;

    const __nv_bfloat16* tAh = Ah + (size_t)b * strideA + (size_t)m0 * lda;
    const __nv_bfloat16* tAl = Al + (size_t)b * strideA + (size_t)m0 * lda;
    const __nv_bfloat16* pBh = Bh + (size_t)b * strideB;
    const __nv_bfloat16* pBl = Bl + (size_t)b * strideB;

    float acc[4][8][4];
    #pragma unroll
    for (int i = 0; i < 4; ++i)
        #pragma unroll
        for (int j = 0; j < 8; ++j)
            #pragma unroll
            for (int q = 0; q < 4; ++q) acc[i][j][q] = 0.0f;

    auto load_stage = [&](int c, int st) {
        const uint32_t base = sb + st * STAGE_BYTES;
        #pragma unroll
        for (int i = 0; i < 8; ++i) {
            int idx = i * 256 + tid;
            int row = idx >> 3, sl = idx & 7;
            uint32_t doff = SWZ128(row * 128 + sl * 16);
            CP_ASYNC16(base + doff,         tAh + (size_t)row * lda + c * 64 + sl * 8);
            CP_ASYNC16(base + 32768 + doff, tAl + (size_t)row * lda + c * 64 + sl * 8);
        }
        if (B_KMAJOR) {
            const __nv_bfloat16* tBh = pBh + (size_t)n0 * ldb;
            const __nv_bfloat16* tBl = pBl + (size_t)n0 * ldb;
            #pragma unroll
            for (int i = 0; i < 4; ++i) {
                int idx = i * 256 + tid;
                int row = idx >> 3, sl = idx & 7;
                uint32_t doff = SWZ128(row * 128 + sl * 16);
                CP_ASYNC16(base + 65536 + doff, tBh + (size_t)row * ldb + c * 64 + sl * 8);
                CP_ASYNC16(base + 81920 + doff, tBl + (size_t)row * ldb + c * 64 + sl * 8);
            }
        } else {
            #pragma unroll
            for (int i = 0; i < 4; ++i) {
                int idx = i * 256 + tid;
                int row = idx >> 4, sl = idx & 15;
                uint32_t doff = SWZ256(row * 256 + sl * 16);
                CP_ASYNC16(base + 65536 + doff, pBh + (size_t)(c * 64 + row) * ldb + n0 + sl * 8);
                CP_ASYNC16(base + 81920 + doff, pBl + (size_t)(c * 64 + row) * ldb + n0 + sl * 8);
            }
        }
        CP_COMMIT();
    };

    load_stage(0, 0);

    for (int c = 0; c < nk; ++c) {
        if (c + 1 < nk) load_stage(c + 1, (c + 1) & 1);
        else            CP_COMMIT();
        CP_WAIT1();
        __syncthreads();

        const uint32_t base = sb + (c & 1) * STAGE_BYTES;
        const uint32_t sAh = base, sAl = base + 32768;
        const uint32_t sBh = base + 65536, sBl = base + 81920;

        #pragma unroll
        for (int ks = 0; ks < 4; ++ks) {
            uint32_t ah[4][4], al[4][4];
            #pragma unroll
            for (int mt = 0; mt < 4; ++mt) {
                int row = warp_m * 64 + mt * 16 + (lane & 15);
                uint32_t off = SWZ128(row * 128 + ks * 32 + ((lane >> 4) << 4));
                LDSM_X4(ah[mt][0], ah[mt][1], ah[mt][2], ah[mt][3], sAh + off);
                LDSM_X4(al[mt][0], al[mt][1], al[mt][2], al[mt][3], sAl + off);
            }
            uint32_t bh[8][2], bl[8][2];
            #pragma unroll
            for (int nt2 = 0; nt2 < 4; ++nt2) {
                if (B_KMAJOR) {
                    int row = warp_n * 64 + nt2 * 16 + ((lane >> 4) << 3) + (lane & 7);
                    uint32_t off = SWZ128(row * 128 + ks * 32 + (((lane >> 3) & 1) << 4));
                    LDSM_X4(bh[2 * nt2][0], bh[2 * nt2][1], bh[2 * nt2 + 1][0], bh[2 * nt2 + 1][1], sBh + off);
                    LDSM_X4(bl[2 * nt2][0], bl[2 * nt2][1], bl[2 * nt2 + 1][0], bl[2 * nt2 + 1][1], sBl + off);
                } else {
                    int krow = ks * 16 + (((lane >> 3) & 1) << 3) + (lane & 7);
                    int col  = warp_n * 64 + nt2 * 16 + ((lane >> 4) << 3);
                    uint32_t off = SWZ256(krow * 256 + col * 2);
                    LDSM_X4T(bh[2 * nt2][0], bh[2 * nt2][1], bh[2 * nt2 + 1][0], bh[2 * nt2 + 1][1], sBh + off);
                    LDSM_X4T(bl[2 * nt2][0], bl[2 * nt2][1], bl[2 * nt2 + 1][0], bl[2 * nt2 + 1][1], sBl + off);
                }
            }
            #pragma unroll
            for (int mt = 0; mt < 4; ++mt)
                #pragma unroll
                for (int nt = 0; nt < 8; ++nt) {
                    MMA_BF16(acc[mt][nt], ah[mt][0], ah[mt][1], ah[mt][2], ah[mt][3], bh[nt][0], bh[nt][1]);
                    MMA_BF16(acc[mt][nt], ah[mt][0], ah[mt][1], ah[mt][2], ah[mt][3], bl[nt][0], bl[nt][1]);
                    MMA_BF16(acc[mt][nt], al[mt][0], al[mt][1], al[mt][2], al[mt][3], bh[nt][0], bh[nt][1]);
                }
        }
        __syncthreads();
    }

    float* Db = D + (size_t)b * strideD;
    #pragma unroll
    for (int mt = 0; mt < 4; ++mt) {
        int row = m0 + warp_m * 64 + mt * 16 + (lane >> 2);
        #pragma unroll
        for (int nt = 0; nt < 8; ++nt) {
            int col = n0 + warp_n * 64 + nt * 8 + (lane & 3) * 2;
            *reinterpret_cast<float2*>(Db + (size_t)row * ldd + col) =
                make_float2(acc[mt][nt][0], acc[mt][nt][1]);
            *reinterpret_cast<float2*>(Db + (size_t)(row + 8) * ldd + col) =
                make_float2(acc[mt][nt][2], acc[mt][nt][3]);
        }
    }
}

// ---------------------------------------------------------------------------
// Softmax over compacted columns j < cnt; emits split probs, zeros elsewhere.
// One warp per (b,l) row. Scores at j >= npad are never written (garbage) —
// the j<cnt selector replaces them before any max/exp.
// ---------------------------------------------------------------------------
__global__ void __launch_bounds__(256) softmax_split()
{
    const int row  = blockIdx.x * 8 + (threadIdx.x >> 5);
    const int lane = threadIdx.x & 31;
    const int b    = row >> 9;
    const int cnt  = g_cnt[b];

    const float* p = g_scores + (size_t)row * S_DIM;

    float4 fv[4];
    float mx = -3e38f;
    #pragma unroll
    for (int c = 0; c < 4; ++c) {
        const int s = c * 128 + lane * 4;
        float4 x = *reinterpret_cast<const float4*>(p + s);
        x.x = (s + 0 < cnt) ? x.x : NEG_INF_F;
        x.y = (s + 1 < cnt) ? x.y : NEG_INF_F;
        x.z = (s + 2 < cnt) ? x.z : NEG_INF_F;
        x.w = (s + 3 < cnt) ? x.w : NEG_INF_F;
        fv[c] = x;
        mx = fmaxf(mx, fmaxf(fmaxf(x.x, x.y), fmaxf(x.z, x.w)));
    }
    #pragma unroll
    for (int o = 16; o > 0; o >>= 1) mx = fmaxf(mx, __shfl_xor_sync(0xffffffffu, mx, o));

    float sum = 0.0f;
    #pragma unroll
    for (int c = 0; c < 4; ++c) {
        fv[c].x = expf(fv[c].x - mx); fv[c].y = expf(fv[c].y - mx);
        fv[c].z = expf(fv[c].z - mx); fv[c].w = expf(fv[c].w - mx);
        sum += fv[c].x + fv[c].y + fv[c].z + fv[c].w;
    }
    #pragma unroll
    for (int o = 16; o > 0; o >>= 1) sum += __shfl_xor_sync(0xffffffffu, sum, o);

    const float inv = 1.0f / sum;
    #pragma unroll
    for (int c = 0; c < 4; ++c) {
        const int s = c * 128 + lane * 4;
        float v0 = fv[c].x * inv, v1 = fv[c].y * inv, v2 = fv[c].z * inv, v3 = fv[c].w * inv;
        __nv_bfloat16 h0, l0, h1, l1, h2, l2, h3, l3;
        split2(v0, h0, l0); split2(v1, h1, l1); split2(v2, h2, l2); split2(v3, h3, l3);
        __nv_bfloat162* ph = reinterpret_cast<__nv_bfloat162*>(g_Ph + (size_t)row * S_DIM + s);
        __nv_bfloat162* pl = reinterpret_cast<__nv_bfloat162*>(g_Pl + (size_t)row * S_DIM + s);
        ph[0] = __nv_bfloat162{h0, h1}; ph[1] = __nv_bfloat162{h2, h3};
        pl[0] = __nv_bfloat162{l0, l1}; pl[1] = __nv_bfloat162{l2, l3};
    }
}

// ---------------------------------------------------------------------------
// Launch
// ---------------------------------------------------------------------------
extern "C" void kernel_launch(void* const* d_in, const int* in_sizes, int n_in,
                              void* d_out, int out_size)
{
    const float* X    = (const float*)d_in[0];   // [B, S, H]
    const int*   mask = (const int*)  d_in[1];   // [B, S]
    const float* W    = (const float*)d_in[2];   // [L, H]
    float* out = (float*)d_out;                  // [B, L, H]

    cudaFuncSetAttribute(gemm_hmma_x3<true, true, false>,
                         cudaFuncAttributeMaxDynamicSharedMemorySize, GEMM_SMEM);
    cudaFuncSetAttribute(gemm_hmma_x3<false, false, true>,
                         cudaFuncAttributeMaxDynamicSharedMemorySize, GEMM_SMEM);

    void *pXh, *pXl, *pWh, *pWl, *pPh, *pPl, *pSc;
    cudaGetSymbolAddress(&pXh, g_Xh); cudaGetSymbolAddress(&pXl, g_Xl);
    cudaGetSymbolAddress(&pWh, g_Wh); cudaGetSymbolAddress(&pWl, g_Wl);
    cudaGetSymbolAddress(&pPh, g_Ph); cudaGetSymbolAddress(&pPl, g_Pl);
    cudaGetSymbolAddress(&pSc, g_scores);

    convert_W<<<(L_DIM * H_DIM) / 1024, 256>>>(W);
    compact_mask<<<B_DIM, 512>>>(mask);
    gather_convert_X<<<dim3(S_DIM, B_DIM), 256>>>(X);

    // GEMM1 (NT, compacted N): scores[b,l,j] = W[l,:] . Xc[b,j,:]
    gemm_hmma_x3<true, true, false><<<dim3(S_DIM / 128, L_DIM / 256, B_DIM), 256, GEMM_SMEM>>>(
        (const __nv_bfloat16*)pWh, (const __nv_bfloat16*)pWl,
        (const __nv_bfloat16*)pXh, (const __nv_bfloat16*)pXl,
        (float*)pSc,
        H_DIM, H_DIM, S_DIM, H_DIM / 64,
        0, (size_t)S_DIM * H_DIM, (size_t)L_DIM * S_DIM);

    softmax_split<<<(B_DIM * L_DIM) / 8, 256>>>();

    // GEMM2 (NN, compacted K): out[b,l,h] = Pc[b,l,:] . Xc[b,:,h]
    gemm_hmma_x3<false, false, true><<<dim3(H_DIM / 128, L_DIM / 256, B_DIM), 256, GEMM_SMEM>>>(
        (const __nv_bfloat16*)pPh, (const __nv_bfloat16*)pPl,
        (const __nv_bfloat16*)pXh, (const __nv_bfloat16*)pXl,
        out,
        S_DIM, H_DIM, H_DIM, 0 /*K_DYN*/,
        (size_t)L_DIM * S_DIM, (size_t)S_DIM * H_DIM, (size_t)L_DIM * H_DIM);
}

// round 8
// speedup vs baseline: 1.6919x; 1.1847x over previous
#include <cuda_runtime.h>
#include <cuda_bf16.h>
#include <stdint.h>

#define B_DIM 64
#define S_DIM 512
#define H_DIM 1024
#define L_DIM 512
#define NEG_INF_F (-1e9f)

// ---------------------------------------------------------------------------
// Scratch (module-load allocations, allowed)
// ---------------------------------------------------------------------------
__device__ float         g_scores[(size_t)B_DIM * L_DIM * S_DIM];
__device__ __nv_bfloat16 g_Xh[(size_t)B_DIM * S_DIM * H_DIM];      // compacted
__device__ __nv_bfloat16 g_Xl[(size_t)B_DIM * S_DIM * H_DIM];
__device__ __nv_bfloat16 g_Wh[(size_t)L_DIM * H_DIM];
__device__ __nv_bfloat16 g_Wl[(size_t)L_DIM * H_DIM];
__device__ __nv_bfloat16 g_Ph[(size_t)B_DIM * L_DIM * S_DIM];      // compacted K
__device__ __nv_bfloat16 g_Pl[(size_t)B_DIM * L_DIM * S_DIM];
__device__ int g_idx[B_DIM * S_DIM];
__device__ int g_cnt[B_DIM];
__device__ int g_npad[B_DIM];          // cnt rounded up to 64

// ---------------------------------------------------------------------------
// Helpers
// ---------------------------------------------------------------------------
__device__ __forceinline__ uint32_t smem_u32(const void* p) {
    uint32_t a;
    asm("{ .reg .u64 t; cvta.to.shared.u64 t, %1; cvt.u32.u64 %0, t; }" : "=r"(a) : "l"(p));
    return a;
}

#define CP_ASYNC16(dst, src) \
    asm volatile("cp.async.cg.shared.global [%0], [%1], 16;" :: "r"(dst), "l"(src))
#define CP_COMMIT()  asm volatile("cp.async.commit_group;" ::: "memory")
#define CP_WAIT1()   asm volatile("cp.async.wait_group 1;" ::: "memory")

#define LDSM_X4(r0, r1, r2, r3, a) \
    asm volatile("ldmatrix.sync.aligned.m8n8.x4.shared.b16 {%0,%1,%2,%3}, [%4];" \
        : "=r"(r0), "=r"(r1), "=r"(r2), "=r"(r3) : "r"(a))
#define LDSM_X4T(r0, r1, r2, r3, a) \
    asm volatile("ldmatrix.sync.aligned.m8n8.x4.trans.shared.b16 {%0,%1,%2,%3}, [%4];" \
        : "=r"(r0), "=r"(r1), "=r"(r2), "=r"(r3) : "r"(a))

#define MMA_BF16(d, a0, a1, a2, a3, b0, b1) \
    asm volatile("mma.sync.aligned.m16n8k16.row.col.f32.bf16.bf16.f32 " \
        "{%0,%1,%2,%3},{%4,%5,%6,%7},{%8,%9},{%0,%1,%2,%3};" \
        : "+f"((d)[0]), "+f"((d)[1]), "+f"((d)[2]), "+f"((d)[3]) \
        : "r"(a0), "r"(a1), "r"(a2), "r"(a3), "r"(b0), "r"(b1))

#define SWZ128(o) ((o) ^ (((o) >> 3) & 0x70))
#define SWZ256(o) ((o) ^ (((o) >> 4) & 0x70))

__device__ __forceinline__ void split2(float v, __nv_bfloat16& h, __nv_bfloat16& l) {
    h = __float2bfloat16(v);
    l = __float2bfloat16(v - __bfloat162float(h));
}

// ---------------------------------------------------------------------------
// Mask compaction: one block of 512 threads per batch.
// ---------------------------------------------------------------------------
__global__ void __launch_bounds__(512) compact_mask(const int* __restrict__ mask) {
    const int b = blockIdx.x, tid = threadIdx.x;
    const int lane = tid & 31, w = tid >> 5;
    const int m = (mask[(size_t)b * S_DIM + tid] != 0);
    const unsigned bal = __ballot_sync(0xffffffffu, m);

    __shared__ int ws[16], woff[16];
    if (lane == 0) ws[w] = __popc(bal);
    __syncthreads();
    if (tid == 0) {
        int s = 0;
        #pragma unroll
        for (int i = 0; i < 16; ++i) { woff[i] = s; s += ws[i]; }
        g_cnt[b]  = s;
        int np = ((s + 63) >> 6) << 6;
        g_npad[b] = (np < 64) ? 64 : np;
    }
    __syncthreads();
    if (m) {
        int pos = woff[w] + __popc(bal & ((1u << lane) - 1u));
        g_idx[b * S_DIM + pos] = tid;
    }
}

// ---------------------------------------------------------------------------
// Gather + split-convert X. Rows j >= npad are never read by either GEMM.
// ---------------------------------------------------------------------------
__global__ void __launch_bounds__(256) gather_convert_X(const float* __restrict__ X) {
    const int j = blockIdx.x, b = blockIdx.y;
    if (j >= g_npad[b]) return;
    const int cnt = g_cnt[b];
    const size_t o = ((size_t)b * S_DIM + j) * H_DIM + threadIdx.x * 4;
    if (j < cnt) {
        const int s = g_idx[b * S_DIM + j];
        float4 v = *reinterpret_cast<const float4*>(X + ((size_t)b * S_DIM + s) * H_DIM + threadIdx.x * 4);
        __nv_bfloat16 h0, l0, h1, l1, h2, l2, h3, l3;
        split2(v.x, h0, l0); split2(v.y, h1, l1); split2(v.z, h2, l2); split2(v.w, h3, l3);
        *reinterpret_cast<__nv_bfloat162*>(g_Xh + o)     = __nv_bfloat162{h0, h1};
        *reinterpret_cast<__nv_bfloat162*>(g_Xh + o + 2) = __nv_bfloat162{h2, h3};
        *reinterpret_cast<__nv_bfloat162*>(g_Xl + o)     = __nv_bfloat162{l0, l1};
        *reinterpret_cast<__nv_bfloat162*>(g_Xl + o + 2) = __nv_bfloat162{l2, l3};
    } else {
        *reinterpret_cast<uint2*>(g_Xh + o) = make_uint2(0, 0);
        *reinterpret_cast<uint2*>(g_Xl + o) = make_uint2(0, 0);
    }
}

__global__ void convert_W(const float* __restrict__ W) {
    size_t i = ((size_t)blockIdx.x * 256 + threadIdx.x) * 4;
    float4 v = *reinterpret_cast<const float4*>(W + i);
    __nv_bfloat16 h0, l0, h1, l1, h2, l2, h3, l3;
    split2(v.x, h0, l0); split2(v.y, h1, l1); split2(v.z, h2, l2); split2(v.w, h3, l3);
    *reinterpret_cast<__nv_bfloat162*>(g_Wh + i)     = __nv_bfloat162{h0, h1};
    *reinterpret_cast<__nv_bfloat162*>(g_Wh + i + 2) = __nv_bfloat162{h2, h3};
    *reinterpret_cast<__nv_bfloat162*>(g_Wl + i)     = __nv_bfloat162{l0, l1};
    *reinterpret_cast<__nv_bfloat162*>(g_Wl + i + 2) = __nv_bfloat162{l2, l3};
}

// ---------------------------------------------------------------------------
// bf16x3 split GEMM via mma.sync. CTA 256(M) x CTA_N, K-chunk 64, 8 warps
// (4M x 2N), warp tile 64 x (CTA_N/2). 2-stage cp.async pipeline.
//   CTA_N=64  + N_LIM: GEMM1, compacted N (exact, npad is a multiple of 64)
//   CTA_N=128 + K_DYN: GEMM2, compacted K
// smem/stage: Ah 32K | Al 32K | Bh CTA_N*128/2... (BHALF = CTA_N*128 bytes/half)
// ---------------------------------------------------------------------------
template <bool B_KMAJOR, bool N_LIM, bool K_DYN, int CTA_N>
__global__ void __launch_bounds__(256, 1) gemm_hmma_x3(
    const __nv_bfloat16* __restrict__ Ah, const __nv_bfloat16* __restrict__ Al,
    const __nv_bfloat16* __restrict__ Bh, const __nv_bfloat16* __restrict__ Bl,
    float* __restrict__ D,
    int lda, int ldb, int ldd, int nk,
    size_t strideA, size_t strideB, size_t strideD)
{
    constexpr int NT    = CTA_N / 16;        // n8-tiles per warp
    constexpr int NT2   = CTA_N / 32;        // ldmatrix.x4 B loads per slice
    constexpr int BHALF = CTA_N * 128;       // bytes per B half-tile
    constexpr int STAGE = 65536 + 2 * BHALF;

    extern __shared__ char smem[];
    const uint32_t sb = smem_u32(smem);
    const int tid = threadIdx.x;
    const int wid = tid >> 5, lane = tid & 31;
    const int warp_m = wid & 3, warp_n = wid >> 2;
    const int b  = blockIdx.z;
    const int m0 = blockIdx.y * 256;
    const int n0 = blockIdx.x * CTA_N;

    if (N_LIM && n0 >= g_npad[b]) return;
    if (K_DYN) nk = g_npad[b] >> 6;

    const __nv_bfloat16* tAh = Ah + (size_t)b * strideA + (size_t)m0 * lda;
    const __nv_bfloat16* tAl = Al + (size_t)b * strideA + (size_t)m0 * lda;
    const __nv_bfloat16* pBh = Bh + (size_t)b * strideB;
    const __nv_bfloat16* pBl = Bl + (size_t)b * strideB;

    float acc[4][NT][4];
    #pragma unroll
    for (int i = 0; i < 4; ++i)
        #pragma unroll
        for (int j = 0; j < NT; ++j)
            #pragma unroll
            for (int q = 0; q < 4; ++q) acc[i][j][q] = 0.0f;

    auto load_stage = [&](int c, int st) {
        const uint32_t base = sb + st * STAGE;
        #pragma unroll
        for (int i = 0; i < 8; ++i) {
            int idx = i * 256 + tid;
            int row = idx >> 3, sl = idx & 7;
            uint32_t doff = SWZ128(row * 128 + sl * 16);
            CP_ASYNC16(base + doff,         tAh + (size_t)row * lda + c * 64 + sl * 8);
            CP_ASYNC16(base + 32768 + doff, tAl + (size_t)row * lda + c * 64 + sl * 8);
        }
        if (B_KMAJOR) {
            const __nv_bfloat16* tBh = pBh + (size_t)n0 * ldb;
            const __nv_bfloat16* tBl = pBl + (size_t)n0 * ldb;
            #pragma unroll
            for (int i = 0; i < NT2; ++i) {
                int idx = i * 256 + tid;
                int row = idx >> 3, sl = idx & 7;
                uint32_t doff = SWZ128(row * 128 + sl * 16);
                CP_ASYNC16(base + 65536 + doff,         tBh + (size_t)row * ldb + c * 64 + sl * 8);
                CP_ASYNC16(base + 65536 + BHALF + doff, tBl + (size_t)row * ldb + c * 64 + sl * 8);
            }
        } else {
            #pragma unroll
            for (int i = 0; i < NT2; ++i) {
                int idx = i * 256 + tid;
                int row = idx >> 4, sl = idx & 15;
                uint32_t doff = SWZ256(row * 256 + sl * 16);
                CP_ASYNC16(base + 65536 + doff,         pBh + (size_t)(c * 64 + row) * ldb + n0 + sl * 8);
                CP_ASYNC16(base + 65536 + BHALF + doff, pBl + (size_t)(c * 64 + row) * ldb + n0 + sl * 8);
            }
        }
        CP_COMMIT();
    };

    load_stage(0, 0);

    for (int c = 0; c < nk; ++c) {
        if (c + 1 < nk) load_stage(c + 1, (c + 1) & 1);
        else            CP_COMMIT();
        CP_WAIT1();
        __syncthreads();

        const uint32_t base = sb + (c & 1) * STAGE;
        const uint32_t sAh = base, sAl = base + 32768;
        const uint32_t sBh = base + 65536, sBl = base + 65536 + BHALF;

        #pragma unroll
        for (int ks = 0; ks < 4; ++ks) {
            uint32_t ah[4][4], al[4][4];
            #pragma unroll
            for (int mt = 0; mt < 4; ++mt) {
                int row = warp_m * 64 + mt * 16 + (lane & 15);
                uint32_t off = SWZ128(row * 128 + ks * 32 + ((lane >> 4) << 4));
                LDSM_X4(ah[mt][0], ah[mt][1], ah[mt][2], ah[mt][3], sAh + off);
                LDSM_X4(al[mt][0], al[mt][1], al[mt][2], al[mt][3], sAl + off);
            }
            uint32_t bh[NT][2], bl[NT][2];
            #pragma unroll
            for (int nt2 = 0; nt2 < NT2; ++nt2) {
                if (B_KMAJOR) {
                    int row = warp_n * (CTA_N / 2) + nt2 * 16 + ((lane >> 4) << 3) + (lane & 7);
                    uint32_t off = SWZ128(row * 128 + ks * 32 + (((lane >> 3) & 1) << 4));
                    LDSM_X4(bh[2 * nt2][0], bh[2 * nt2][1], bh[2 * nt2 + 1][0], bh[2 * nt2 + 1][1], sBh + off);
                    LDSM_X4(bl[2 * nt2][0], bl[2 * nt2][1], bl[2 * nt2 + 1][0], bl[2 * nt2 + 1][1], sBl + off);
                } else {
                    int krow = ks * 16 + (((lane >> 3) & 1) << 3) + (lane & 7);
                    int col  = warp_n * (CTA_N / 2) + nt2 * 16 + ((lane >> 4) << 3);
                    uint32_t off = SWZ256(krow * 256 + col * 2);
                    LDSM_X4T(bh[2 * nt2][0], bh[2 * nt2][1], bh[2 * nt2 + 1][0], bh[2 * nt2 + 1][1], sBh + off);
                    LDSM_X4T(bl[2 * nt2][0], bl[2 * nt2][1], bl[2 * nt2 + 1][0], bl[2 * nt2 + 1][1], sBl + off);
                }
            }
            #pragma unroll
            for (int mt = 0; mt < 4; ++mt)
                #pragma unroll
                for (int nt = 0; nt < NT; ++nt) {
                    MMA_BF16(acc[mt][nt], ah[mt][0], ah[mt][1], ah[mt][2], ah[mt][3], bh[nt][0], bh[nt][1]);
                    MMA_BF16(acc[mt][nt], ah[mt][0], ah[mt][1], ah[mt][2], ah[mt][3], bl[nt][0], bl[nt][1]);
                    MMA_BF16(acc[mt][nt], al[mt][0], al[mt][1], al[mt][2], al[mt][3], bh[nt][0], bh[nt][1]);
                }
        }
        __syncthreads();
    }

    float* Db = D + (size_t)b * strideD;
    #pragma unroll
    for (int mt = 0; mt < 4; ++mt) {
        int row = m0 + warp_m * 64 + mt * 16 + (lane >> 2);
        #pragma unroll
        for (int nt = 0; nt < NT; ++nt) {
            int col = n0 + warp_n * (CTA_N / 2) + nt * 8 + (lane & 3) * 2;
            *reinterpret_cast<float2*>(Db + (size_t)row * ldd + col) =
                make_float2(acc[mt][nt][0], acc[mt][nt][1]);
            *reinterpret_cast<float2*>(Db + (size_t)(row + 8) * ldd + col) =
                make_float2(acc[mt][nt][2], acc[mt][nt][3]);
        }
    }
}

// ---------------------------------------------------------------------------
// Softmax over compacted columns j < cnt; skips 128-col chunks >= npad
// entirely (neither read nor written — nothing downstream reads them).
// ---------------------------------------------------------------------------
__global__ void __launch_bounds__(256) softmax_split()
{
    const int row  = blockIdx.x * 8 + (threadIdx.x >> 5);
    const int lane = threadIdx.x & 31;
    const int b    = row >> 9;
    const int cnt  = g_cnt[b];
    const int npad = g_npad[b];

    const float* p = g_scores + (size_t)row * S_DIM;

    float4 fv[4];
    float mx = -3e38f;
    #pragma unroll
    for (int c = 0; c < 4; ++c) {
        if (c * 128 < npad) {
            const int s = c * 128 + lane * 4;
            float4 x = *reinterpret_cast<const float4*>(p + s);
            x.x = (s + 0 < cnt) ? x.x : NEG_INF_F;
            x.y = (s + 1 < cnt) ? x.y : NEG_INF_F;
            x.z = (s + 2 < cnt) ? x.z : NEG_INF_F;
            x.w = (s + 3 < cnt) ? x.w : NEG_INF_F;
            fv[c] = x;
            mx = fmaxf(mx, fmaxf(fmaxf(x.x, x.y), fmaxf(x.z, x.w)));
        } else {
            fv[c] = make_float4(NEG_INF_F, NEG_INF_F, NEG_INF_F, NEG_INF_F);
        }
    }
    #pragma unroll
    for (int o = 16; o > 0; o >>= 1) mx = fmaxf(mx, __shfl_xor_sync(0xffffffffu, mx, o));

    float sum = 0.0f;
    #pragma unroll
    for (int c = 0; c < 4; ++c) {
        if (c * 128 < npad) {
            fv[c].x = expf(fv[c].x - mx); fv[c].y = expf(fv[c].y - mx);
            fv[c].z = expf(fv[c].z - mx); fv[c].w = expf(fv[c].w - mx);
            sum += fv[c].x + fv[c].y + fv[c].z + fv[c].w;
        }
    }
    #pragma unroll
    for (int o = 16; o > 0; o >>= 1) sum += __shfl_xor_sync(0xffffffffu, sum, o);

    const float inv = 1.0f / sum;
    #pragma unroll
    for (int c = 0; c < 4; ++c) {
        if (c * 128 < npad) {
            const int s = c * 128 + lane * 4;
            float v0 = fv[c].x * inv, v1 = fv[c].y * inv, v2 = fv[c].z * inv, v3 = fv[c].w * inv;
            __nv_bfloat16 h0, l0, h1, l1, h2, l2, h3, l3;
            split2(v0, h0, l0); split2(v1, h1, l1); split2(v2, h2, l2); split2(v3, h3, l3);
            __nv_bfloat162* ph = reinterpret_cast<__nv_bfloat162*>(g_Ph + (size_t)row * S_DIM + s);
            __nv_bfloat162* pl = reinterpret_cast<__nv_bfloat162*>(g_Pl + (size_t)row * S_DIM + s);
            ph[0] = __nv_bfloat162{h0, h1}; ph[1] = __nv_bfloat162{h2, h3};
            pl[0] = __nv_bfloat162{l0, l1}; pl[1] = __nv_bfloat162{l2, l3};
        }
    }
}

// ---------------------------------------------------------------------------
// Launch
// ---------------------------------------------------------------------------
#define GEMM1_SMEM (2 * (65536 + 2 * (64 * 128)))    // 163840
#define GEMM2_SMEM (2 * (65536 + 2 * (128 * 128)))   // 196608

extern "C" void kernel_launch(void* const* d_in, const int* in_sizes, int n_in,
                              void* d_out, int out_size)
{
    const float* X    = (const float*)d_in[0];   // [B, S, H]
    const int*   mask = (const int*)  d_in[1];   // [B, S]
    const float* W    = (const float*)d_in[2];   // [L, H]
    float* out = (float*)d_out;                  // [B, L, H]

    cudaFuncSetAttribute(gemm_hmma_x3<true, true, false, 64>,
                         cudaFuncAttributeMaxDynamicSharedMemorySize, GEMM1_SMEM);
    cudaFuncSetAttribute(gemm_hmma_x3<false, false, true, 128>,
                         cudaFuncAttributeMaxDynamicSharedMemorySize, GEMM2_SMEM);

    void *pXh, *pXl, *pWh, *pWl, *pPh, *pPl, *pSc;
    cudaGetSymbolAddress(&pXh, g_Xh); cudaGetSymbolAddress(&pXl, g_Xl);
    cudaGetSymbolAddress(&pWh, g_Wh); cudaGetSymbolAddress(&pWl, g_Wl);
    cudaGetSymbolAddress(&pPh, g_Ph); cudaGetSymbolAddress(&pPl, g_Pl);
    cudaGetSymbolAddress(&pSc, g_scores);

    convert_W<<<(L_DIM * H_DIM) / 1024, 256>>>(W);
    compact_mask<<<B_DIM, 512>>>(mask);
    gather_convert_X<<<dim3(S_DIM, B_DIM), 256>>>(X);

    // GEMM1 (NT, compacted N, exact): scores[b,l,j] = W[l,:] . Xc[b,j,:]
    gemm_hmma_x3<true, true, false, 64><<<dim3(S_DIM / 64, L_DIM / 256, B_DIM), 256, GEMM1_SMEM>>>(
        (const __nv_bfloat16*)pWh, (const __nv_bfloat16*)pWl,
        (const __nv_bfloat16*)pXh, (const __nv_bfloat16*)pXl,
        (float*)pSc,
        H_DIM, H_DIM, S_DIM, H_DIM / 64,
        0, (size_t)S_DIM * H_DIM, (size_t)L_DIM * S_DIM);

    softmax_split<<<(B_DIM * L_DIM) / 8, 256>>>();

    // GEMM2 (NN, compacted K): out[b,l,h] = Pc[b,l,:] . Xc[b,:,h]
    gemm_hmma_x3<false, false, true, 128><<<dim3(H_DIM / 128, L_DIM / 256, B_DIM), 256, GEMM2_SMEM>>>(
        (const __nv_bfloat16*)pPh, (const __nv_bfloat16*)pPl,
        (const __nv_bfloat16*)pXh, (const __nv_bfloat16*)pXl,
        out,
        S_DIM, H_DIM, H_DIM, 0 /*K_DYN*/,
        (size_t)L_DIM * S_DIM, (size_t)S_DIM * H_DIM, (size_t)L_DIM * H_DIM);
}

// round 9
// speedup vs baseline: 1.7826x; 1.0536x over previous
#include <cuda_runtime.h>
#include <cuda_bf16.h>
#include <stdint.h>

#define B_DIM 64
#define S_DIM 512
#define H_DIM 1024
#define L_DIM 512
#define NEG_INF_F (-1e9f)

// ---------------------------------------------------------------------------
// Scratch (module-load allocations, allowed)
// ---------------------------------------------------------------------------
__device__ float         g_scores[(size_t)B_DIM * L_DIM * S_DIM];
__device__ __nv_bfloat16 g_Xh[(size_t)B_DIM * S_DIM * H_DIM];      // compacted
__device__ __nv_bfloat16 g_Xl[(size_t)B_DIM * S_DIM * H_DIM];
__device__ __nv_bfloat16 g_Wh[(size_t)L_DIM * H_DIM];
__device__ __nv_bfloat16 g_Wl[(size_t)L_DIM * H_DIM];
__device__ __nv_bfloat16 g_Ph[(size_t)B_DIM * L_DIM * S_DIM];      // compacted K
__device__ __nv_bfloat16 g_Pl[(size_t)B_DIM * L_DIM * S_DIM];
__device__ int g_idx[B_DIM * S_DIM];
__device__ int g_cnt[B_DIM];
__device__ int g_npad[B_DIM];          // cnt rounded up to 64

// ---------------------------------------------------------------------------
// Helpers
// ---------------------------------------------------------------------------
__device__ __forceinline__ uint32_t smem_u32(const void* p) {
    uint32_t a;
    asm("{ .reg .u64 t; cvta.to.shared.u64 t, %1; cvt.u32.u64 %0, t; }" : "=r"(a) : "l"(p));
    return a;
}

#define CP_ASYNC16(dst, src) \
    asm volatile("cp.async.cg.shared.global [%0], [%1], 16;" :: "r"(dst), "l"(src))
#define CP_COMMIT()  asm volatile("cp.async.commit_group;" ::: "memory")
#define CP_WAIT1()   asm volatile("cp.async.wait_group 1;" ::: "memory")

#define LDSM_X4(r0, r1, r2, r3, a) \
    asm volatile("ldmatrix.sync.aligned.m8n8.x4.shared.b16 {%0,%1,%2,%3}, [%4];" \
        : "=r"(r0), "=r"(r1), "=r"(r2), "=r"(r3) : "r"(a))
#define LDSM_X4T(r0, r1, r2, r3, a) \
    asm volatile("ldmatrix.sync.aligned.m8n8.x4.trans.shared.b16 {%0,%1,%2,%3}, [%4];" \
        : "=r"(r0), "=r"(r1), "=r"(r2), "=r"(r3) : "r"(a))

#define MMA_BF16(d, a0, a1, a2, a3, b0, b1) \
    asm volatile("mma.sync.aligned.m16n8k16.row.col.f32.bf16.bf16.f32 " \
        "{%0,%1,%2,%3},{%4,%5,%6,%7},{%8,%9},{%0,%1,%2,%3};" \
        : "+f"((d)[0]), "+f"((d)[1]), "+f"((d)[2]), "+f"((d)[3]) \
        : "r"(a0), "r"(a1), "r"(a2), "r"(a3), "r"(b0), "r"(b1))

#define SWZ128(o) ((o) ^ (((o) >> 3) & 0x70))

__device__ __forceinline__ void split2(float v, __nv_bfloat16& h, __nv_bfloat16& l) {
    h = __float2bfloat16(v);
    l = __float2bfloat16(v - __bfloat162float(h));
}

// ---------------------------------------------------------------------------
// Mask compaction: one block of 512 threads per batch.
// ---------------------------------------------------------------------------
__global__ void __launch_bounds__(512) compact_mask(const int* __restrict__ mask) {
    const int b = blockIdx.x, tid = threadIdx.x;
    const int lane = tid & 31, w = tid >> 5;
    const int m = (mask[(size_t)b * S_DIM + tid] != 0);
    const unsigned bal = __ballot_sync(0xffffffffu, m);

    __shared__ int ws[16], woff[16];
    if (lane == 0) ws[w] = __popc(bal);
    __syncthreads();
    if (tid == 0) {
        int s = 0;
        #pragma unroll
        for (int i = 0; i < 16; ++i) { woff[i] = s; s += ws[i]; }
        g_cnt[b]  = s;
        int np = ((s + 63) >> 6) << 6;
        g_npad[b] = (np < 64) ? 64 : np;
    }
    __syncthreads();
    if (m) {
        int pos = woff[w] + __popc(bal & ((1u << lane) - 1u));
        g_idx[b * S_DIM + pos] = tid;
    }
}

// ---------------------------------------------------------------------------
// Gather + split-convert X. Rows j >= npad are never read by either GEMM.
// ---------------------------------------------------------------------------
__global__ void __launch_bounds__(256) gather_convert_X(const float* __restrict__ X) {
    const int j = blockIdx.x, b = blockIdx.y;
    if (j >= g_npad[b]) return;
    const int cnt = g_cnt[b];
    const size_t o = ((size_t)b * S_DIM + j) * H_DIM + threadIdx.x * 4;
    if (j < cnt) {
        const int s = g_idx[b * S_DIM + j];
        float4 v = *reinterpret_cast<const float4*>(X + ((size_t)b * S_DIM + s) * H_DIM + threadIdx.x * 4);
        __nv_bfloat16 h0, l0, h1, l1, h2, l2, h3, l3;
        split2(v.x, h0, l0); split2(v.y, h1, l1); split2(v.z, h2, l2); split2(v.w, h3, l3);
        *reinterpret_cast<__nv_bfloat162*>(g_Xh + o)     = __nv_bfloat162{h0, h1};
        *reinterpret_cast<__nv_bfloat162*>(g_Xh + o + 2) = __nv_bfloat162{h2, h3};
        *reinterpret_cast<__nv_bfloat162*>(g_Xl + o)     = __nv_bfloat162{l0, l1};
        *reinterpret_cast<__nv_bfloat162*>(g_Xl + o + 2) = __nv_bfloat162{l2, l3};
    } else {
        *reinterpret_cast<uint2*>(g_Xh + o) = make_uint2(0, 0);
        *reinterpret_cast<uint2*>(g_Xl + o) = make_uint2(0, 0);
    }
}

__global__ void convert_W(const float* __restrict__ W) {
    size_t i = ((size_t)blockIdx.x * 256 + threadIdx.x) * 4;
    float4 v = *reinterpret_cast<const float4*>(W + i);
    __nv_bfloat16 h0, l0, h1, l1, h2, l2, h3, l3;
    split2(v.x, h0, l0); split2(v.y, h1, l1); split2(v.z, h2, l2); split2(v.w, h3, l3);
    *reinterpret_cast<__nv_bfloat162*>(g_Wh + i)     = __nv_bfloat162{h0, h1};
    *reinterpret_cast<__nv_bfloat162*>(g_Wh + i + 2) = __nv_bfloat162{h2, h3};
    *reinterpret_cast<__nv_bfloat162*>(g_Wl + i)     = __nv_bfloat162{l0, l1};
    *reinterpret_cast<__nv_bfloat162*>(g_Wl + i + 2) = __nv_bfloat162{l2, l3};
}

// ---------------------------------------------------------------------------
// bf16x3 split GEMM via mma.sync. CTA 128(M) x 64(N), K-chunk 64, 8 warps
// (4M x 2N), warp tile 32x32. 2-stage cp.async pipeline, 2 CTAs/SM.
//   N_LIM: GEMM1 (B K-major), skip CTA if n0 >= npad; N granularity = exact
//   K_DYN: GEMM2 (B row-major, 64-col/128B rows), nk = npad/64
// smem/stage: Ah 16K | Al 16K | Bh 8K | Bl 8K = 48KB; 2 stages = 96KB.
// ---------------------------------------------------------------------------
#define STAGE_BYTES 49152
#define GEMM_SMEM   (2 * STAGE_BYTES)

template <bool B_KMAJOR, bool N_LIM, bool K_DYN>
__global__ void __launch_bounds__(256, 2) gemm_hmma_x3(
    const __nv_bfloat16* __restrict__ Ah, const __nv_bfloat16* __restrict__ Al,
    const __nv_bfloat16* __restrict__ Bh, const __nv_bfloat16* __restrict__ Bl,
    float* __restrict__ D,
    int lda, int ldb, int ldd, int nk,
    size_t strideA, size_t strideB, size_t strideD)
{
    extern __shared__ char smem[];
    const uint32_t sb = smem_u32(smem);
    const int tid = threadIdx.x;
    const int wid = tid >> 5, lane = tid & 31;
    const int warp_m = wid & 3, warp_n = wid >> 2;   // 4M x 2N
    const int b  = blockIdx.z;
    const int m0 = blockIdx.y * 128;
    const int n0 = blockIdx.x * 64;

    if (N_LIM && n0 >= g_npad[b]) return;
    if (K_DYN) nk = g_npad[b] >> 6;

    const __nv_bfloat16* tAh = Ah + (size_t)b * strideA + (size_t)m0 * lda;
    const __nv_bfloat16* tAl = Al + (size_t)b * strideA + (size_t)m0 * lda;
    const __nv_bfloat16* pBh = Bh + (size_t)b * strideB;
    const __nv_bfloat16* pBl = Bl + (size_t)b * strideB;

    float acc[2][4][4];
    #pragma unroll
    for (int i = 0; i < 2; ++i)
        #pragma unroll
        for (int j = 0; j < 4; ++j)
            #pragma unroll
            for (int q = 0; q < 4; ++q) acc[i][j][q] = 0.0f;

    auto load_stage = [&](int c, int st) {
        const uint32_t base = sb + st * STAGE_BYTES;
        // A halves: 128 rows x 64 k (128B rows) = 1024 slices each
        #pragma unroll
        for (int i = 0; i < 4; ++i) {
            int idx = i * 256 + tid;
            int row = idx >> 3, sl = idx & 7;
            uint32_t doff = SWZ128(row * 128 + sl * 16);
            CP_ASYNC16(base + doff,         tAh + (size_t)row * lda + c * 64 + sl * 8);
            CP_ASYNC16(base + 16384 + doff, tAl + (size_t)row * lda + c * 64 + sl * 8);
        }
        // B halves: 64 rows x 128B = 512 slices each
        #pragma unroll
        for (int i = 0; i < 2; ++i) {
            int idx = i * 256 + tid;
            int row = idx >> 3, sl = idx & 7;
            uint32_t doff = SWZ128(row * 128 + sl * 16);
            if (B_KMAJOR) {
                CP_ASYNC16(base + 32768 + doff, pBh + (size_t)(n0 + row) * ldb + c * 64 + sl * 8);
                CP_ASYNC16(base + 40960 + doff, pBl + (size_t)(n0 + row) * ldb + c * 64 + sl * 8);
            } else {
                CP_ASYNC16(base + 32768 + doff, pBh + (size_t)(c * 64 + row) * ldb + n0 + sl * 8);
                CP_ASYNC16(base + 40960 + doff, pBl + (size_t)(c * 64 + row) * ldb + n0 + sl * 8);
            }
        }
        CP_COMMIT();
    };

    load_stage(0, 0);

    for (int c = 0; c < nk; ++c) {
        if (c + 1 < nk) load_stage(c + 1, (c + 1) & 1);
        else            CP_COMMIT();
        CP_WAIT1();
        __syncthreads();

        const uint32_t base = sb + (c & 1) * STAGE_BYTES;
        const uint32_t sAh = base, sAl = base + 16384;
        const uint32_t sBh = base + 32768, sBl = base + 40960;

        #pragma unroll
        for (int ks = 0; ks < 4; ++ks) {
            uint32_t ah[2][4], al[2][4];
            #pragma unroll
            for (int mt = 0; mt < 2; ++mt) {
                int row = warp_m * 32 + mt * 16 + (lane & 15);
                uint32_t off = SWZ128(row * 128 + ks * 32 + ((lane >> 4) << 4));
                LDSM_X4(ah[mt][0], ah[mt][1], ah[mt][2], ah[mt][3], sAh + off);
                LDSM_X4(al[mt][0], al[mt][1], al[mt][2], al[mt][3], sAl + off);
            }
            uint32_t bh[4][2], bl[4][2];
            #pragma unroll
            for (int nt2 = 0; nt2 < 2; ++nt2) {
                if (B_KMAJOR) {
                    int row = warp_n * 32 + nt2 * 16 + ((lane >> 4) << 3) + (lane & 7);
                    uint32_t off = SWZ128(row * 128 + ks * 32 + (((lane >> 3) & 1) << 4));
                    LDSM_X4(bh[2 * nt2][0], bh[2 * nt2][1], bh[2 * nt2 + 1][0], bh[2 * nt2 + 1][1], sBh + off);
                    LDSM_X4(bl[2 * nt2][0], bl[2 * nt2][1], bl[2 * nt2 + 1][0], bl[2 * nt2 + 1][1], sBl + off);
                } else {
                    int krow = ks * 16 + (((lane >> 3) & 1) << 3) + (lane & 7);
                    int col  = warp_n * 32 + nt2 * 16 + ((lane >> 4) << 3);
                    uint32_t off = SWZ128(krow * 128 + col * 2);
                    LDSM_X4T(bh[2 * nt2][0], bh[2 * nt2][1], bh[2 * nt2 + 1][0], bh[2 * nt2 + 1][1], sBh + off);
                    LDSM_X4T(bl[2 * nt2][0], bl[2 * nt2][1], bl[2 * nt2 + 1][0], bl[2 * nt2 + 1][1], sBl + off);
                }
            }
            #pragma unroll
            for (int mt = 0; mt < 2; ++mt)
                #pragma unroll
                for (int nt = 0; nt < 4; ++nt) {
                    MMA_BF16(acc[mt][nt], ah[mt][0], ah[mt][1], ah[mt][2], ah[mt][3], bh[nt][0], bh[nt][1]);
                    MMA_BF16(acc[mt][nt], ah[mt][0], ah[mt][1], ah[mt][2], ah[mt][3], bl[nt][0], bl[nt][1]);
                    MMA_BF16(acc[mt][nt], al[mt][0], al[mt][1], al[mt][2], al[mt][3], bh[nt][0], bh[nt][1]);
                }
        }
        __syncthreads();
    }

    float* Db = D + (size_t)b * strideD;
    #pragma unroll
    for (int mt = 0; mt < 2; ++mt) {
        int row = m0 + warp_m * 32 + mt * 16 + (lane >> 2);
        #pragma unroll
        for (int nt = 0; nt < 4; ++nt) {
            int col = n0 + warp_n * 32 + nt * 8 + (lane & 3) * 2;
            *reinterpret_cast<float2*>(Db + (size_t)row * ldd + col) =
                make_float2(acc[mt][nt][0], acc[mt][nt][1]);
            *reinterpret_cast<float2*>(Db + (size_t)(row + 8) * ldd + col) =
                make_float2(acc[mt][nt][2], acc[mt][nt][3]);
        }
    }
}

// ---------------------------------------------------------------------------
// Softmax over compacted columns j < cnt; skips 128-col chunks >= npad.
// ---------------------------------------------------------------------------
__global__ void __launch_bounds__(256) softmax_split()
{
    const int row  = blockIdx.x * 8 + (threadIdx.x >> 5);
    const int lane = threadIdx.x & 31;
    const int b    = row >> 9;
    const int cnt  = g_cnt[b];
    const int npad = g_npad[b];

    const float* p = g_scores + (size_t)row * S_DIM;

    float4 fv[4];
    float mx = -3e38f;
    #pragma unroll
    for (int c = 0; c < 4; ++c) {
        if (c * 128 < npad) {
            const int s = c * 128 + lane * 4;
            float4 x = *reinterpret_cast<const float4*>(p + s);
            x.x = (s + 0 < cnt) ? x.x : NEG_INF_F;
            x.y = (s + 1 < cnt) ? x.y : NEG_INF_F;
            x.z = (s + 2 < cnt) ? x.z : NEG_INF_F;
            x.w = (s + 3 < cnt) ? x.w : NEG_INF_F;
            fv[c] = x;
            mx = fmaxf(mx, fmaxf(fmaxf(x.x, x.y), fmaxf(x.z, x.w)));
        } else {
            fv[c] = make_float4(NEG_INF_F, NEG_INF_F, NEG_INF_F, NEG_INF_F);
        }
    }
    #pragma unroll
    for (int o = 16; o > 0; o >>= 1) mx = fmaxf(mx, __shfl_xor_sync(0xffffffffu, mx, o));

    float sum = 0.0f;
    #pragma unroll
    for (int c = 0; c < 4; ++c) {
        if (c * 128 < npad) {
            fv[c].x = expf(fv[c].x - mx); fv[c].y = expf(fv[c].y - mx);
            fv[c].z = expf(fv[c].z - mx); fv[c].w = expf(fv[c].w - mx);
            sum += fv[c].x + fv[c].y + fv[c].z + fv[c].w;
        }
    }
    #pragma unroll
    for (int o = 16; o > 0; o >>= 1) sum += __shfl_xor_sync(0xffffffffu, sum, o);

    const float inv = 1.0f / sum;
    #pragma unroll
    for (int c = 0; c < 4; ++c) {
        if (c * 128 < npad) {
            const int s = c * 128 + lane * 4;
            float v0 = fv[c].x * inv, v1 = fv[c].y * inv, v2 = fv[c].z * inv, v3 = fv[c].w * inv;
            __nv_bfloat16 h0, l0, h1, l1, h2, l2, h3, l3;
            split2(v0, h0, l0); split2(v1, h1, l1); split2(v2, h2, l2); split2(v3, h3, l3);
            __nv_bfloat162* ph = reinterpret_cast<__nv_bfloat162*>(g_Ph + (size_t)row * S_DIM + s);
            __nv_bfloat162* pl = reinterpret_cast<__nv_bfloat162*>(g_Pl + (size_t)row * S_DIM + s);
            ph[0] = __nv_bfloat162{h0, h1}; ph[1] = __nv_bfloat162{h2, h3};
            pl[0] = __nv_bfloat162{l0, l1}; pl[1] = __nv_bfloat162{l2, l3};
        }
    }
}

// ---------------------------------------------------------------------------
// Launch
// ---------------------------------------------------------------------------
extern "C" void kernel_launch(void* const* d_in, const int* in_sizes, int n_in,
                              void* d_out, int out_size)
{
    const float* X    = (const float*)d_in[0];   // [B, S, H]
    const int*   mask = (const int*)  d_in[1];   // [B, S]
    const float* W    = (const float*)d_in[2];   // [L, H]
    float* out = (float*)d_out;                  // [B, L, H]

    cudaFuncSetAttribute(gemm_hmma_x3<true, true, false>,
                         cudaFuncAttributeMaxDynamicSharedMemorySize, GEMM_SMEM);
    cudaFuncSetAttribute(gemm_hmma_x3<false, false, true>,
                         cudaFuncAttributeMaxDynamicSharedMemorySize, GEMM_SMEM);

    void *pXh, *pXl, *pWh, *pWl, *pPh, *pPl, *pSc;
    cudaGetSymbolAddress(&pXh, g_Xh); cudaGetSymbolAddress(&pXl, g_Xl);
    cudaGetSymbolAddress(&pWh, g_Wh); cudaGetSymbolAddress(&pWl, g_Wl);
    cudaGetSymbolAddress(&pPh, g_Ph); cudaGetSymbolAddress(&pPl, g_Pl);
    cudaGetSymbolAddress(&pSc, g_scores);

    convert_W<<<(L_DIM * H_DIM) / 1024, 256>>>(W);
    compact_mask<<<B_DIM, 512>>>(mask);
    gather_convert_X<<<dim3(S_DIM, B_DIM), 256>>>(X);

    // GEMM1 (NT, compacted N, exact): scores[b,l,j] = W[l,:] . Xc[b,j,:]
    gemm_hmma_x3<true, true, false><<<dim3(S_DIM / 64, L_DIM / 128, B_DIM), 256, GEMM_SMEM>>>(
        (const __nv_bfloat16*)pWh, (const __nv_bfloat16*)pWl,
        (const __nv_bfloat16*)pXh, (const __nv_bfloat16*)pXl,
        (float*)pSc,
        H_DIM, H_DIM, S_DIM, H_DIM / 64,
        0, (size_t)S_DIM * H_DIM, (size_t)L_DIM * S_DIM);

    softmax_split<<<(B_DIM * L_DIM) / 8, 256>>>();

    // GEMM2 (NN, compacted K): out[b,l,h] = Pc[b,l,:] . Xc[b,:,h]
    gemm_hmma_x3<false, false, true><<<dim3(H_DIM / 64, L_DIM / 128, B_DIM), 256, GEMM_SMEM>>>(
        (const __nv_bfloat16*)pPh, (const __nv_bfloat16*)pPl,
        (const __nv_bfloat16*)pXh, (const __nv_bfloat16*)pXl,
        out,
        S_DIM, H_DIM, H_DIM, 0 /*K_DYN*/,
        (size_t)L_DIM * S_DIM, (size_t)S_DIM * H_DIM, (size_t)L_DIM * H_DIM);
}